// round 1
// baseline (speedup 1.0000x reference)
#include <cuda_runtime.h>
#include <math.h>

#define BSZ 16384
#define HD 512
#define NL 3
#define HD4 (4*HD)

#define BM 128
#define BN 64
#define BK 16

// ---------------- scratch (device globals; no allocation allowed) ----------------
__device__ float d_Wc[6*HD*HD];            // combined attn weight per (gen,layer)
__device__ float d_wvT[6*HD*HD];           // transposed wv
__device__ float d_bc[6*HD];               // combined attn bias
__device__ int   d_cnt[2];                 // compacted row counts
__device__ int   d_idx[2][BSZ];            // compact -> full row
__device__ int   d_pos[2][BSZ];            // full row -> compact (valid only when mt matches)
__device__ float d_srcC[(size_t)BSZ*HD];
__device__ float d_tgtC[(size_t)BSZ*HD];
__device__ float d_xbuf[(size_t)BSZ*HD];
__device__ float d_t1  [(size_t)BSZ*HD];
__device__ float d_hbuf[(size_t)BSZ*HD4];
__device__ float d_genb[2][(size_t)BSZ*HD];
__device__ float d_prior_h[2*HD];
__device__ float d_prior  [2*HD];

__device__ __forceinline__ float gelu_exact(float x){
    return 0.5f*x*(1.0f+erff(x*0.70710678118654752440f));
}

// ---------------- generic fp32 GEMM: C[M,N] = A[M,K] @ W[N,K]^T + bias ----------------
// EPI: 0 = none, 1 = exact gelu. M dynamic via cntPtr (or static if cntPtr==nullptr).
template<int EPI>
__global__ void __launch_bounds__(256) gemm_kernel(
    const float* __restrict__ A, const float* __restrict__ Wt,
    const float* __restrict__ bias, float* __restrict__ C,
    int N, int K, int Mstatic, const int* __restrict__ cntPtr)
{
    const int Mv = cntPtr ? *cntPtr : Mstatic;
    const int m0 = blockIdx.y * BM;
    if (m0 >= Mv) return;
    const int n0 = blockIdx.x * BN;
    const int tid = threadIdx.x;

    __shared__ float As[BK][BM+4];
    __shared__ float Ws[BK][BN+4];

    float acc[8][4];
    #pragma unroll
    for (int j=0;j<8;j++)
        #pragma unroll
        for (int q=0;q<4;q++) acc[j][q]=0.f;

    const int ty = tid >> 4;   // 0..15 -> 8 rows each
    const int tx = tid & 15;   // 0..15 -> 4 cols each

    for (int k0=0;k0<K;k0+=BK){
        #pragma unroll
        for (int r=0;r<2;r++){
            int t = tid + r*256;
            int m = t >> 2, kv = t & 3;
            float4 av = *(const float4*)&A[(size_t)(m0+m)*K + k0 + kv*4];
            As[kv*4+0][m]=av.x; As[kv*4+1][m]=av.y; As[kv*4+2][m]=av.z; As[kv*4+3][m]=av.w;
        }
        {
            int n = tid >> 2, kv = tid & 3;
            float4 wv = *(const float4*)&Wt[(size_t)(n0+n)*K + k0 + kv*4];
            Ws[kv*4+0][n]=wv.x; Ws[kv*4+1][n]=wv.y; Ws[kv*4+2][n]=wv.z; Ws[kv*4+3][n]=wv.w;
        }
        __syncthreads();
        #pragma unroll
        for (int k=0;k<BK;k++){
            float a[8], b[4];
            #pragma unroll
            for (int j=0;j<8;j++) a[j]=As[k][ty*8+j];
            #pragma unroll
            for (int q=0;q<4;q++) b[q]=Ws[k][tx*4+q];
            #pragma unroll
            for (int j=0;j<8;j++)
                #pragma unroll
                for (int q=0;q<4;q++)
                    acc[j][q] = fmaf(a[j], b[q], acc[j][q]);
        }
        __syncthreads();
    }

    float bv[4];
    #pragma unroll
    for (int q=0;q<4;q++) bv[q] = bias ? bias[n0+tx*4+q] : 0.f;
    #pragma unroll
    for (int j=0;j<8;j++){
        int m = m0 + ty*8 + j;
        if (m < Mv){
            float v0=acc[j][0]+bv[0], v1=acc[j][1]+bv[1], v2=acc[j][2]+bv[2], v3=acc[j][3]+bv[3];
            if (EPI==1){ v0=gelu_exact(v0); v1=gelu_exact(v1); v2=gelu_exact(v2); v3=gelu_exact(v3); }
            float4 o; o.x=v0; o.y=v1; o.z=v2; o.w=v3;
            *(float4*)&C[(size_t)m*N + n0 + tx*4] = o;
        }
    }
}

// ---------------- LayerNorm(x + y) * g + b, row-wise over HD=512 ----------------
__global__ void __launch_bounds__(128) ln_add_kernel(
    const float* __restrict__ X, const float* __restrict__ Y,
    const float* __restrict__ g, const float* __restrict__ bb,
    float* __restrict__ out, const int* __restrict__ cntPtr)
{
    int row = blockIdx.x;
    if (row >= *cntPtr) return;
    int t = threadIdx.x;
    float4 v = ((const float4*)X)[(size_t)row*128 + t];
    float4 y = ((const float4*)Y)[(size_t)row*128 + t];
    v.x+=y.x; v.y+=y.y; v.z+=y.z; v.w+=y.w;
    float s  = v.x+v.y+v.z+v.w;
    float sq = v.x*v.x+v.y*v.y+v.z*v.z+v.w*v.w;
    __shared__ float red[8];
    #pragma unroll
    for (int off=16;off;off>>=1){
        s  += __shfl_down_sync(0xffffffffu,s,off);
        sq += __shfl_down_sync(0xffffffffu,sq,off);
    }
    int warp = t>>5, lane = t&31;
    if (lane==0){ red[warp]=s; red[warp+4]=sq; }
    __syncthreads();
    if (t==0){
        float S=red[0]+red[1]+red[2]+red[3];
        float Q=red[4]+red[5]+red[6]+red[7];
        float mean=S*(1.f/512.f);
        float var =Q*(1.f/512.f) - mean*mean;
        red[0]=mean; red[1]=rsqrtf(var + 1e-5f);
    }
    __syncthreads();
    float mean=red[0], rs=red[1];
    float4 gg=((const float4*)g)[t], bv=((const float4*)bb)[t];
    float4 o;
    o.x=(v.x-mean)*rs*gg.x+bv.x;
    o.y=(v.y-mean)*rs*gg.y+bv.y;
    o.z=(v.z-mean)*rs*gg.z+bv.z;
    o.w=(v.w-mean)*rs*gg.w+bv.w;
    ((float4*)out)[(size_t)row*128+t]=o;
}

// ---------------- compaction ----------------
__global__ void build_index_kernel(const int* __restrict__ mt)
{
    if (threadIdx.x==0){ d_cnt[0]=0; d_cnt[1]=0; }
    __syncthreads();
    for (int b=threadIdx.x; b<BSZ; b+=blockDim.x){
        int m = mt[b];
        if (m==1){ int p=atomicAdd(&d_cnt[0],1); d_idx[0][p]=b; d_pos[0][b]=p; }
        else if (m==2){ int p=atomicAdd(&d_cnt[1],1); d_idx[1][p]=b; d_pos[1][b]=p; }
    }
}

__global__ void __launch_bounds__(128) gather_kernel(
    const float* __restrict__ src, const float* __restrict__ tgt, int gi)
{
    int c = blockIdx.x;
    if (c >= d_cnt[gi]) return;
    int r = d_idx[gi][c];
    int t = threadIdx.x;
    ((float4*)d_srcC)[(size_t)c*128+t] = ((const float4*)src)[(size_t)r*128+t];
    ((float4*)d_tgtC)[(size_t)c*128+t] = ((const float4*)tgt)[(size_t)r*128+t];
}

// ---------------- weight preprocessing ----------------
// transpose wv (rows 2H..3H of qkv_w[i][l]) into d_wvT[z]
__global__ void transpose_wv_kernel(const float* __restrict__ qkv_w)
{
    __shared__ float tile[32][33];
    int bz = blockIdx.z;
    const float* src = qkv_w + (size_t)bz*3*HD*HD + (size_t)2*HD*HD;
    int j0 = blockIdx.y*32, k0 = blockIdx.x*32;
    int tx = threadIdx.x, ty = threadIdx.y;
    #pragma unroll
    for (int r=0;r<32;r+=8)
        tile[ty+r][tx] = src[(size_t)(j0+ty+r)*HD + k0+tx];
    __syncthreads();
    float* dst = d_wvT + (size_t)bz*HD*HD;
    #pragma unroll
    for (int r=0;r<32;r+=8)
        dst[(size_t)(k0+ty+r)*HD + j0+tx] = tile[tx][ty+r];
}

// bc[z][n] = sum_j ao_w[z][n,j]*bv[z][j] + ao_b[z][n]
__global__ void bc_kernel(const float* __restrict__ ao_w,
                          const float* __restrict__ ao_b,
                          const float* __restrict__ qkv_b)
{
    int z = blockIdx.x;
    const float* ao = ao_w + (size_t)z*HD*HD;
    const float* bv = qkv_b + (size_t)z*3*HD + 2*HD;
    int warp = threadIdx.x>>5, lane = threadIdx.x&31;
    for (int n=warp; n<HD; n+=8){
        float s=0.f;
        for (int j=lane;j<HD;j+=32) s += ao[(size_t)n*HD+j]*bv[j];
        #pragma unroll
        for (int off=16;off;off>>=1) s += __shfl_down_sync(0xffffffffu,s,off);
        if (lane==0) d_bc[(size_t)z*HD+n] = s + ao_b[(size_t)z*HD+n];
    }
}

// ---------------- tiny prior MLP (1 row) ----------------
__global__ void prior_mm_kernel(const float* __restrict__ x, const float* __restrict__ W,
                                const float* __restrict__ b, float* __restrict__ out,
                                int K, int N, int dogelu)
{
    int gw = (blockIdx.x*blockDim.x + threadIdx.x)>>5;
    int lane = threadIdx.x & 31;
    if (gw >= N) return;
    float s=0.f;
    for (int k=lane;k<K;k+=32) s += x[k]*W[(size_t)gw*K+k];
    #pragma unroll
    for (int off=16;off;off>>=1) s += __shfl_down_sync(0xffffffffu,s,off);
    if (lane==0){ s += b[gw]; out[gw] = dogelu ? gelu_exact(s) : s; }
}

// ---------------- final selection + residual blend ----------------
__global__ void __launch_bounds__(128) final_kernel(
    const float* __restrict__ img, const float* __restrict__ text,
    const int* __restrict__ mtA, const float* __restrict__ rw,
    float* __restrict__ out)
{
    int b = blockIdx.x, t = threadIdx.x;
    int mt = mtA[b];
    float4 iv = ((const float4*)img )[(size_t)b*128+t];
    float4 tv = ((const float4*)text)[(size_t)b*128+t];
    float4 oi = iv, ot = tv;
    if (mt==3){
        oi = ((const float4*)d_prior)[t];
        ot = ((const float4*)d_prior)[128+t];
    } else if (mt==2){
        float r = rw[1], q = 1.f - r;
        float4 gv = ((const float4*)d_genb[1])[(size_t)d_pos[1][b]*128+t];
        oi.x=r*iv.x+q*gv.x; oi.y=r*iv.y+q*gv.y; oi.z=r*iv.z+q*gv.z; oi.w=r*iv.w+q*gv.w;
    } else if (mt==1){
        float r = rw[0], q = 1.f - r;
        float4 gv = ((const float4*)d_genb[0])[(size_t)d_pos[0][b]*128+t];
        ot.x=r*tv.x+q*gv.x; ot.y=r*tv.y+q*gv.y; ot.z=r*tv.z+q*gv.z; ot.w=r*tv.w+q*gv.w;
    }
    ((float4*)out)[(size_t)b*128+t] = oi;
    ((float4*)out)[(size_t)BSZ*128 + (size_t)b*128+t] = ot;
}

// ---------------- host orchestration ----------------
extern "C" void kernel_launch(void* const* d_in, const int* in_sizes, int n_in,
                              void* d_out, int out_size)
{
    const float* img  = (const float*)d_in[0];
    const float* text = (const float*)d_in[1];
    const float* ipw  = (const float*)d_in[2];
    const float* ipb  = (const float*)d_in[3];
    const float* qkvw = (const float*)d_in[4];
    const float* qkvb = (const float*)d_in[5];
    const float* aow  = (const float*)d_in[6];
    const float* aob  = (const float*)d_in[7];
    const float* ln1g = (const float*)d_in[8];
    const float* ln1b = (const float*)d_in[9];
    const float* ln2g = (const float*)d_in[10];
    const float* ln2b = (const float*)d_in[11];
    const float* f1w  = (const float*)d_in[12];
    const float* f1b  = (const float*)d_in[13];
    const float* f2w  = (const float*)d_in[14];
    const float* f2b  = (const float*)d_in[15];
    const float* opw  = (const float*)d_in[16];
    const float* opb  = (const float*)d_in[17];
    const float* rw   = (const float*)d_in[18];
    const float* pw1  = (const float*)d_in[19];
    const float* pb1  = (const float*)d_in[20];
    const float* pw2  = (const float*)d_in[21];
    const float* pb2  = (const float*)d_in[22];
    const float* pemb = (const float*)d_in[23];
    const int*   mt   = (const int*)d_in[24];
    float* out = (float*)d_out;

    void* p;
    cudaGetSymbolAddress(&p, d_Wc);      float* Wc   = (float*)p;
    cudaGetSymbolAddress(&p, d_wvT);     float* wvT  = (float*)p;
    cudaGetSymbolAddress(&p, d_bc);      float* bc   = (float*)p;
    cudaGetSymbolAddress(&p, d_cnt);     int*   cnt  = (int*)p;
    cudaGetSymbolAddress(&p, d_srcC);    float* srcC = (float*)p;
    cudaGetSymbolAddress(&p, d_tgtC);    float* tgtC = (float*)p;
    cudaGetSymbolAddress(&p, d_xbuf);    float* xb   = (float*)p;
    cudaGetSymbolAddress(&p, d_t1);      float* t1   = (float*)p;
    cudaGetSymbolAddress(&p, d_hbuf);    float* hb   = (float*)p;
    cudaGetSymbolAddress(&p, d_genb);    float* genb = (float*)p;
    cudaGetSymbolAddress(&p, d_prior_h); float* ph   = (float*)p;
    cudaGetSymbolAddress(&p, d_prior);   float* pr   = (float*)p;

    // 1) compaction + weight prep + prior (independent small work)
    build_index_kernel<<<1,256>>>(mt);
    transpose_wv_kernel<<<dim3(16,16,6), dim3(32,8)>>>(qkvw);
    for (int z=0;z<6;z++){
        gemm_kernel<0><<<dim3(HD/BN, (HD+BM-1)/BM), 256>>>(
            aow + (size_t)z*HD*HD, wvT + (size_t)z*HD*HD, nullptr,
            Wc + (size_t)z*HD*HD, HD, HD, HD, nullptr);
    }
    bc_kernel<<<6,256>>>(aow, aob, qkvb);
    prior_mm_kernel<<<128,256>>>(pemb, pw1, pb1, ph, HD,   2*HD, 1);
    prior_mm_kernel<<<128,256>>>(ph,   pw2, pb2, pr, 2*HD, 2*HD, 0);

    // 2) two generators on compacted rows
    const dim3 gN512 (HD /BN, BSZ/BM);
    const dim3 gN2048(HD4/BN, BSZ/BM);
    for (int i=0;i<2;i++){
        const float* src = (i==0) ? img  : text;
        const float* tgt = (i==0) ? text : img;
        const int* cp = cnt + i;
        gather_kernel<<<BSZ,128>>>(src, tgt, i);
        // x = srcC @ ipw.T + ipb
        gemm_kernel<0><<<gN512,256>>>(srcC, ipw + (size_t)i*HD*HD, ipb + (size_t)i*HD,
                                      xb, HD, HD, 0, cp);
        for (int l=0;l<NL;l++){
            int z = i*NL + l;
            // attn (collapsed): t1 = tgtC @ Wc.T + bc
            gemm_kernel<0><<<gN512,256>>>(tgtC, Wc + (size_t)z*HD*HD, bc + (size_t)z*HD,
                                          t1, HD, HD, 0, cp);
            ln_add_kernel<<<BSZ,128>>>(xb, t1, ln1g + (size_t)z*HD, ln1b + (size_t)z*HD, xb, cp);
            // h = gelu(x @ f1w.T + f1b)
            gemm_kernel<1><<<gN2048,256>>>(xb, f1w + (size_t)z*HD4*HD, f1b + (size_t)z*HD4,
                                           hb, HD4, HD, 0, cp);
            // t1 = h @ f2w.T + f2b
            gemm_kernel<0><<<gN512,256>>>(hb, f2w + (size_t)z*HD*HD4, f2b + (size_t)z*HD,
                                          t1, HD, HD4, 0, cp);
            ln_add_kernel<<<BSZ,128>>>(xb, t1, ln2g + (size_t)z*HD, ln2b + (size_t)z*HD, xb, cp);
        }
        // gen core = x @ opw.T + opb
        gemm_kernel<0><<<gN512,256>>>(xb, opw + (size_t)i*HD*HD, opb + (size_t)i*HD,
                                      genb + (size_t)i*BSZ*HD, HD, HD, 0, cp);
    }

    // 3) final selection/blend writes the entire output
    final_kernel<<<BSZ,128>>>(img, text, mt, rw, out);
}

// round 2
// speedup vs baseline: 1.9180x; 1.9180x over previous
#include <cuda_runtime.h>
#include <mma.h>
#include <math.h>
using namespace nvcuda;

#define BSZ 16384
#define HD 512
#define NL 3
#define HD4 2048
#define SEG BSZ            // row stride between generator segments in scratch

#define BM 128
#define BN 128
#define BK 32
#define LDT 36             // smem leading dim (pad)

// ---------------- scratch (device globals; no allocation allowed) ----------------
__device__ float d_Wc[6*HD*HD];
__device__ float d_wvT[6*HD*HD];
__device__ float d_bc[6*HD];
__device__ int   d_cnt[2];
__device__ int   d_idx[2][BSZ];
__device__ int   d_pos[2][BSZ];
__device__ float d_srcC[(size_t)2*SEG*HD];
__device__ float d_tgtC[(size_t)2*SEG*HD];
__device__ float d_xbuf[(size_t)2*SEG*HD];
__device__ float d_t1  [(size_t)2*SEG*HD];
__device__ float d_hbuf[(size_t)2*SEG*HD4];
__device__ float d_genb[(size_t)2*SEG*HD];
__device__ float d_prior_h[2*HD];
__device__ float d_prior  [2*HD];

__device__ __forceinline__ float gelu_exact(float x){
    return 0.5f*x*(1.0f+erff(x*0.70710678118654752440f));
}

// ---------------- TF32 tensor-core GEMM ----------------
// C[z][M,N] = A[z][M,K] @ W[z][N,K]^T + bias[z][N]   (z = blockIdx.z)
// EPI: 0 = none, 1 = exact gelu. M dynamic via cnt[z] (or Mstatic if cnt==nullptr).
template<int EPI>
__global__ void __launch_bounds__(256, 2) mm_tf32(
    const float* __restrict__ A, size_t As_,
    const float* __restrict__ W, size_t Ws_,
    const float* __restrict__ bias, size_t bs_,
    float* __restrict__ C, size_t Cs_,
    int N, int K, int Mstatic, const int* __restrict__ cnt)
{
    const int z  = blockIdx.z;
    const int Mv = cnt ? cnt[z] : Mstatic;
    const int m0 = blockIdx.y * BM;
    if (m0 >= Mv) return;
    const int n0 = blockIdx.x * BN;
    A += (size_t)z * As_;
    W += (size_t)z * Ws_;
    C += (size_t)z * Cs_;
    const float* bptr = bias ? (bias + (size_t)z * bs_) : nullptr;

    __shared__ float Asm[BM][LDT];
    __shared__ float Bsm[BN][LDT];
    __shared__ float cbuf[8][16][20];

    const int tid  = threadIdx.x;
    const int wid  = tid >> 5;
    const int lane = tid & 31;
    const int wm   = wid & 1;    // 2 warp-rows of 64
    const int wn   = wid >> 1;   // 4 warp-cols of 32

    wmma::fragment<wmma::accumulator,16,16,8,float> acc[4][2];
    #pragma unroll
    for (int i=0;i<4;i++)
        #pragma unroll
        for (int j=0;j<2;j++) wmma::fill_fragment(acc[i][j], 0.f);

    for (int k0=0;k0<K;k0+=BK){
        // stage A and W tiles, rounding to tf32 in smem
        #pragma unroll
        for (int it=0;it<4;it++){
            int idx = tid + it*256;          // 0..1023
            int r   = idx >> 3;              // 0..127
            int kq  = (idx & 7) * 4;         // 0,4,...,28
            float4 av = *(const float4*)&A[(size_t)(m0+r)*K + k0 + kq];
            Asm[r][kq+0]=wmma::__float_to_tf32(av.x);
            Asm[r][kq+1]=wmma::__float_to_tf32(av.y);
            Asm[r][kq+2]=wmma::__float_to_tf32(av.z);
            Asm[r][kq+3]=wmma::__float_to_tf32(av.w);
            float4 wv = *(const float4*)&W[(size_t)(n0+r)*K + k0 + kq];
            Bsm[r][kq+0]=wmma::__float_to_tf32(wv.x);
            Bsm[r][kq+1]=wmma::__float_to_tf32(wv.y);
            Bsm[r][kq+2]=wmma::__float_to_tf32(wv.z);
            Bsm[r][kq+3]=wmma::__float_to_tf32(wv.w);
        }
        __syncthreads();
        #pragma unroll
        for (int kk=0;kk<BK;kk+=8){
            wmma::fragment<wmma::matrix_a,16,16,8,wmma::precision::tf32,wmma::row_major> af[4];
            wmma::fragment<wmma::matrix_b,16,16,8,wmma::precision::tf32,wmma::col_major> bf[2];
            #pragma unroll
            for (int i=0;i<4;i++) wmma::load_matrix_sync(af[i], &Asm[wm*64 + i*16][kk], LDT);
            #pragma unroll
            for (int j=0;j<2;j++) wmma::load_matrix_sync(bf[j], &Bsm[wn*32 + j*16][kk], LDT);
            #pragma unroll
            for (int i=0;i<4;i++)
                #pragma unroll
                for (int j=0;j<2;j++)
                    wmma::mma_sync(acc[i][j], af[i], bf[j], acc[i][j]);
        }
        __syncthreads();
    }

    // epilogue: stage each 16x16 fragment through per-warp smem, add bias (+gelu), store
    #pragma unroll
    for (int i=0;i<4;i++){
        #pragma unroll
        for (int j=0;j<2;j++){
            wmma::store_matrix_sync(&cbuf[wid][0][0], acc[i][j], 20, wmma::mem_row_major);
            __syncwarp();
            int r  = lane >> 1;            // 0..15
            int cq = (lane & 1) * 8;       // 0 or 8
            int m  = m0 + wm*64 + i*16 + r;
            if (m < Mv){
                int nb = n0 + wn*32 + j*16 + cq;
                float v[8];
                #pragma unroll
                for (int c=0;c<8;c++){
                    float x = cbuf[wid][r][cq+c];
                    if (bptr) x += bptr[nb+c];
                    v[c] = (EPI==1) ? gelu_exact(x) : x;
                }
                float4 o0 = make_float4(v[0],v[1],v[2],v[3]);
                float4 o1 = make_float4(v[4],v[5],v[6],v[7]);
                *(float4*)&C[(size_t)m*N + nb    ] = o0;
                *(float4*)&C[(size_t)m*N + nb + 4] = o1;
            }
            __syncwarp();
        }
    }
}

// ---------------- LayerNorm(x + y) * g + b over HD=512, batched over gens ----------------
__global__ void __launch_bounds__(128) ln_add_kernel(
    const float* __restrict__ X, const float* __restrict__ Y,
    const float* __restrict__ g0, const float* __restrict__ b0,
    int l, float* __restrict__ out, const int* __restrict__ cntPtr)
{
    int gen = blockIdx.y;
    if ((int)blockIdx.x >= cntPtr[gen]) return;
    size_t row = (size_t)gen*SEG + blockIdx.x;
    const float* g  = g0 + (size_t)(gen*NL + l)*HD;
    const float* bb = b0 + (size_t)(gen*NL + l)*HD;
    int t = threadIdx.x;
    float4 v = ((const float4*)X)[row*128 + t];
    float4 y = ((const float4*)Y)[row*128 + t];
    v.x+=y.x; v.y+=y.y; v.z+=y.z; v.w+=y.w;
    float s  = v.x+v.y+v.z+v.w;
    float sq = v.x*v.x+v.y*v.y+v.z*v.z+v.w*v.w;
    __shared__ float red[8];
    #pragma unroll
    for (int off=16;off;off>>=1){
        s  += __shfl_down_sync(0xffffffffu,s,off);
        sq += __shfl_down_sync(0xffffffffu,sq,off);
    }
    int warp = t>>5, lane = t&31;
    if (lane==0){ red[warp]=s; red[warp+4]=sq; }
    __syncthreads();
    if (t==0){
        float S=red[0]+red[1]+red[2]+red[3];
        float Q=red[4]+red[5]+red[6]+red[7];
        float mean=S*(1.f/512.f);
        float var =Q*(1.f/512.f) - mean*mean;
        red[0]=mean; red[1]=rsqrtf(var + 1e-5f);
    }
    __syncthreads();
    float mean=red[0], rs=red[1];
    float4 gg=((const float4*)g)[t], bv=((const float4*)bb)[t];
    float4 o;
    o.x=(v.x-mean)*rs*gg.x+bv.x;
    o.y=(v.y-mean)*rs*gg.y+bv.y;
    o.z=(v.z-mean)*rs*gg.z+bv.z;
    o.w=(v.w-mean)*rs*gg.w+bv.w;
    ((float4*)out)[row*128+t]=o;
}

// ---------------- compaction ----------------
__global__ void build_index_kernel(const int* __restrict__ mt)
{
    if (threadIdx.x==0){ d_cnt[0]=0; d_cnt[1]=0; }
    __syncthreads();
    for (int b=threadIdx.x; b<BSZ; b+=blockDim.x){
        int m = mt[b];
        if (m==1){ int p=atomicAdd(&d_cnt[0],1); d_idx[0][p]=b; d_pos[0][b]=p; }
        else if (m==2){ int p=atomicAdd(&d_cnt[1],1); d_idx[1][p]=b; d_pos[1][b]=p; }
    }
}

__global__ void __launch_bounds__(128) gather_kernel(
    const float* __restrict__ img, const float* __restrict__ text)
{
    int gi = blockIdx.y;
    int c  = blockIdx.x;
    if (c >= d_cnt[gi]) return;
    int r = d_idx[gi][c];
    const float* src = gi ? text : img;
    const float* tgt = gi ? img  : text;
    int t = threadIdx.x;
    size_t drow = (size_t)gi*SEG + c;
    ((float4*)d_srcC)[drow*128+t] = ((const float4*)src)[(size_t)r*128+t];
    ((float4*)d_tgtC)[drow*128+t] = ((const float4*)tgt)[(size_t)r*128+t];
}

// ---------------- weight preprocessing ----------------
__global__ void transpose_wv_kernel(const float* __restrict__ qkv_w)
{
    __shared__ float tile[32][33];
    int bz = blockIdx.z;
    const float* src = qkv_w + (size_t)bz*3*HD*HD + (size_t)2*HD*HD;
    int j0 = blockIdx.y*32, k0 = blockIdx.x*32;
    int tx = threadIdx.x, ty = threadIdx.y;
    #pragma unroll
    for (int r=0;r<32;r+=8)
        tile[ty+r][tx] = src[(size_t)(j0+ty+r)*HD + k0+tx];
    __syncthreads();
    float* dst = d_wvT + (size_t)bz*HD*HD;
    #pragma unroll
    for (int r=0;r<32;r+=8)
        dst[(size_t)(k0+ty+r)*HD + j0+tx] = tile[tx][ty+r];
}

__global__ void bc_kernel(const float* __restrict__ ao_w,
                          const float* __restrict__ ao_b,
                          const float* __restrict__ qkv_b)
{
    int z = blockIdx.x;
    const float* ao = ao_w + (size_t)z*HD*HD;
    const float* bv = qkv_b + (size_t)z*3*HD + 2*HD;
    int warp = threadIdx.x>>5, lane = threadIdx.x&31;
    for (int n=warp; n<HD; n+=8){
        float s=0.f;
        for (int j=lane;j<HD;j+=32) s += ao[(size_t)n*HD+j]*bv[j];
        #pragma unroll
        for (int off=16;off;off>>=1) s += __shfl_down_sync(0xffffffffu,s,off);
        if (lane==0) d_bc[(size_t)z*HD+n] = s + ao_b[(size_t)z*HD+n];
    }
}

// ---------------- tiny prior MLP (1 row) ----------------
__global__ void prior_mm_kernel(const float* __restrict__ x, const float* __restrict__ W,
                                const float* __restrict__ b, float* __restrict__ out,
                                int K, int N, int dogelu)
{
    int gw = (blockIdx.x*blockDim.x + threadIdx.x)>>5;
    int lane = threadIdx.x & 31;
    if (gw >= N) return;
    float s=0.f;
    for (int k=lane;k<K;k+=32) s += x[k]*W[(size_t)gw*K+k];
    #pragma unroll
    for (int off=16;off;off>>=1) s += __shfl_down_sync(0xffffffffu,s,off);
    if (lane==0){ s += b[gw]; out[gw] = dogelu ? gelu_exact(s) : s; }
}

// ---------------- final selection + residual blend ----------------
__global__ void __launch_bounds__(128) final_kernel(
    const float* __restrict__ img, const float* __restrict__ text,
    const int* __restrict__ mtA, const float* __restrict__ rw,
    float* __restrict__ out)
{
    int b = blockIdx.x, t = threadIdx.x;
    int mt = mtA[b];
    float4 iv = ((const float4*)img )[(size_t)b*128+t];
    float4 tv = ((const float4*)text)[(size_t)b*128+t];
    float4 oi = iv, ot = tv;
    if (mt==3){
        oi = ((const float4*)d_prior)[t];
        ot = ((const float4*)d_prior)[128+t];
    } else if (mt==2){
        float r = rw[1], q = 1.f - r;
        float4 gv = ((const float4*)d_genb)[((size_t)SEG + d_pos[1][b])*128+t];
        oi.x=r*iv.x+q*gv.x; oi.y=r*iv.y+q*gv.y; oi.z=r*iv.z+q*gv.z; oi.w=r*iv.w+q*gv.w;
    } else if (mt==1){
        float r = rw[0], q = 1.f - r;
        float4 gv = ((const float4*)d_genb)[(size_t)d_pos[0][b]*128+t];
        ot.x=r*tv.x+q*gv.x; ot.y=r*tv.y+q*gv.y; ot.z=r*tv.z+q*gv.z; ot.w=r*tv.w+q*gv.w;
    }
    ((float4*)out)[(size_t)b*128+t] = oi;
    ((float4*)out)[(size_t)BSZ*128 + (size_t)b*128+t] = ot;
}

// ---------------- host orchestration ----------------
extern "C" void kernel_launch(void* const* d_in, const int* in_sizes, int n_in,
                              void* d_out, int out_size)
{
    const float* img  = (const float*)d_in[0];
    const float* text = (const float*)d_in[1];
    const float* ipw  = (const float*)d_in[2];
    const float* ipb  = (const float*)d_in[3];
    const float* qkvw = (const float*)d_in[4];
    const float* qkvb = (const float*)d_in[5];
    const float* aow  = (const float*)d_in[6];
    const float* aob  = (const float*)d_in[7];
    const float* ln1g = (const float*)d_in[8];
    const float* ln1b = (const float*)d_in[9];
    const float* ln2g = (const float*)d_in[10];
    const float* ln2b = (const float*)d_in[11];
    const float* f1w  = (const float*)d_in[12];
    const float* f1b  = (const float*)d_in[13];
    const float* f2w  = (const float*)d_in[14];
    const float* f2b  = (const float*)d_in[15];
    const float* opw  = (const float*)d_in[16];
    const float* opb  = (const float*)d_in[17];
    const float* rw   = (const float*)d_in[18];
    const float* pw1  = (const float*)d_in[19];
    const float* pb1  = (const float*)d_in[20];
    const float* pw2  = (const float*)d_in[21];
    const float* pb2  = (const float*)d_in[22];
    const float* pemb = (const float*)d_in[23];
    const int*   mt   = (const int*)d_in[24];
    float* out = (float*)d_out;

    void* p;
    cudaGetSymbolAddress(&p, d_Wc);      float* Wc   = (float*)p;
    cudaGetSymbolAddress(&p, d_wvT);     float* wvT  = (float*)p;
    cudaGetSymbolAddress(&p, d_bc);      float* bc   = (float*)p;
    cudaGetSymbolAddress(&p, d_cnt);     int*   cnt  = (int*)p;
    cudaGetSymbolAddress(&p, d_srcC);    float* srcC = (float*)p;
    cudaGetSymbolAddress(&p, d_tgtC);    float* tgtC = (float*)p;
    cudaGetSymbolAddress(&p, d_xbuf);    float* xb   = (float*)p;
    cudaGetSymbolAddress(&p, d_t1);      float* t1   = (float*)p;
    cudaGetSymbolAddress(&p, d_hbuf);    float* hb   = (float*)p;
    cudaGetSymbolAddress(&p, d_genb);    float* genb = (float*)p;
    cudaGetSymbolAddress(&p, d_prior_h); float* ph   = (float*)p;
    cudaGetSymbolAddress(&p, d_prior);   float* pr   = (float*)p;

    const size_t HH   = (size_t)HD*HD;
    const size_t SH   = (size_t)SEG*HD;
    const size_t SH4  = (size_t)SEG*HD4;

    // 1) compaction + weight prep + prior
    build_index_kernel<<<1,256>>>(mt);
    transpose_wv_kernel<<<dim3(16,16,6), dim3(32,8)>>>(qkvw);
    mm_tf32<0><<<dim3(HD/BN, HD/BM, 6), 256>>>(
        aow, HH, wvT, HH, nullptr, 0, Wc, HH, HD, HD, HD, nullptr);
    bc_kernel<<<6,256>>>(aow, aob, qkvb);
    prior_mm_kernel<<<128,256>>>(pemb, pw1, pb1, ph, HD,   2*HD, 1);
    prior_mm_kernel<<<128,256>>>(ph,   pw2, pb2, pr, 2*HD, 2*HD, 0);

    // 2) both generators batched over z=2 on compacted rows
    gather_kernel<<<dim3(BSZ,2),128>>>(img, text);

    const dim3 gN512 (HD /BN, BSZ/BM, 2);
    const dim3 gN2048(HD4/BN, BSZ/BM, 2);
    const dim3 gLN   (BSZ, 2);

    // x = srcC @ ipw.T + ipb
    mm_tf32<0><<<gN512,256>>>(srcC, SH, ipw, HH, ipb, HD, xb, SH, HD, HD, 0, cnt);
    for (int l=0;l<NL;l++){
        // collapsed attention: t1 = tgtC @ Wc[l].T + bc[l]
        mm_tf32<0><<<gN512,256>>>(tgtC, SH, Wc + (size_t)l*HH, (size_t)NL*HH,
                                  bc + (size_t)l*HD, (size_t)NL*HD, t1, SH, HD, HD, 0, cnt);
        ln_add_kernel<<<gLN,128>>>(xb, t1, ln1g, ln1b, l, xb, cnt);
        // h = gelu(x @ f1w.T + f1b)
        mm_tf32<1><<<gN2048,256>>>(xb, SH, f1w + (size_t)l*HD4*HD, (size_t)NL*HD4*HD,
                                   f1b + (size_t)l*HD4, (size_t)NL*HD4, hb, SH4, HD4, HD, 0, cnt);
        // t1 = h @ f2w.T + f2b
        mm_tf32<0><<<gN512,256>>>(hb, SH4, f2w + (size_t)l*HD*HD4, (size_t)NL*HD*HD4,
                                  f2b + (size_t)l*HD, (size_t)NL*HD, t1, SH, HD, HD4, 0, cnt);
        ln_add_kernel<<<gLN,128>>>(xb, t1, ln2g, ln2b, l, xb, cnt);
    }
    // gen core = x @ opw.T + opb
    mm_tf32<0><<<gN512,256>>>(xb, SH, opw, HH, opb, HD, genb, SH, HD, HD, 0, cnt);

    // 3) final selection/blend
    final_kernel<<<BSZ,128>>>(img, text, mt, rw, out);
}

// round 4
// speedup vs baseline: 1.9729x; 1.0286x over previous
#include <cuda_runtime.h>
#include <mma.h>
#include <math.h>
#include <cstdint>
#include <stdint.h>
using namespace nvcuda;

#define BSZ 16384
#define HD 512
#define NL 3
#define HD4 2048
#define SEG BSZ

#define BM 128
#define BN 128
#define BK 32
#define PAD 36                       // smem row stride in floats (144B, 16B-aligned)
#define STAGE_FLOATS (2*128*PAD)     // A+B tiles for one stage
#define SMEM_BYTES (2*STAGE_FLOATS*4)

// ---------------- scratch ----------------
__device__ float d_Wc[6*HD*HD];
__device__ float d_wvT[6*HD*HD];
__device__ float d_bc[6*HD];
__device__ int   d_cnt[2];
__device__ int   d_idx[2][BSZ];
__device__ int   d_pos[2][BSZ];
__device__ float d_srcC[(size_t)2*SEG*HD];
__device__ float d_tgtC[(size_t)2*SEG*HD];
__device__ float d_xbuf[(size_t)2*SEG*HD];
__device__ float d_t1  [(size_t)2*SEG*HD];
__device__ float d_hbuf[(size_t)2*SEG*HD4];
__device__ float d_genb[(size_t)2*SEG*HD];
__device__ float d_prior_h[2*HD];
__device__ float d_prior  [2*HD];

__device__ __forceinline__ float gelu_exact(float x){
    return 0.5f*x*(1.0f+erff(x*0.70710678118654752440f));
}

__device__ __forceinline__ void cpasync16(unsigned int s, const void* g){
    asm volatile("cp.async.cg.shared.global [%0], [%1], 16;\n" :: "r"(s), "l"(g));
}
__device__ __forceinline__ void cpasync_commit(){
    asm volatile("cp.async.commit_group;\n");
}

// ---------------- TF32 tensor-core GEMM, cp.async double-buffered ----------------
// C[z][M,N] = A[z][M,K] @ W[z][N,K]^T + bias[z][N]
template<int EPI>
__global__ void __launch_bounds__(256, 2) mm_tf32(
    const float* __restrict__ A, size_t As_,
    const float* __restrict__ W, size_t Ws_,
    const float* __restrict__ bias, size_t bs_,
    float* __restrict__ C, size_t Cs_,
    int N, int K, int Mstatic, const int* __restrict__ cnt)
{
    const int z  = blockIdx.z;
    const int Mv = cnt ? cnt[z] : Mstatic;
    const int m0 = blockIdx.y * BM;
    if (m0 >= Mv) return;
    const int n0 = blockIdx.x * BN;
    A += (size_t)z * As_;
    W += (size_t)z * Ws_;
    C += (size_t)z * Cs_;
    const float* bptr = bias ? (bias + (size_t)z * bs_) : nullptr;

    extern __shared__ float smem[];
    const unsigned int smem_u32 = (unsigned int)__cvta_generic_to_shared(smem);

    const int tid  = threadIdx.x;
    const int wid  = tid >> 5;
    const int lane = tid & 31;
    const int wm   = wid & 1;    // 2 warp-rows of 64
    const int wn   = wid >> 1;   // 4 warp-cols of 32

    wmma::fragment<wmma::accumulator,16,16,8,float> acc[4][2];
    #pragma unroll
    for (int i=0;i<4;i++)
        #pragma unroll
        for (int j=0;j<2;j++) wmma::fill_fragment(acc[i][j], 0.f);

    // per-thread load coords: 4 chunks of 16B for A, 4 for B
    // chunk c = tid + it*256 -> row = c>>3 (0..127), kq = (c&7)*4
    auto load_stage = [&](int s, int k0){
        const unsigned int base = smem_u32 + (unsigned int)(s*STAGE_FLOATS*4);
        #pragma unroll
        for (int it=0; it<4; it++){
            int c  = tid + it*256;
            int r  = c >> 3;
            int kq = (c & 7) * 4;
            unsigned int off = (unsigned int)((r*PAD + kq)*4);
            cpasync16(base + off,                              &A[(size_t)(m0+r)*K + k0 + kq]);
            cpasync16(base + (unsigned int)(128*PAD*4) + off,  &W[(size_t)(n0+r)*K + k0 + kq]);
        }
        cpasync_commit();
    };

    load_stage(0, 0);
    int stage = 0;
    for (int k0=0; k0<K; k0+=BK){
        if (k0 + BK < K){
            load_stage(stage^1, k0+BK);
            asm volatile("cp.async.wait_group 1;\n");
        } else {
            asm volatile("cp.async.wait_group 0;\n");
        }
        __syncthreads();

        const float* Asb = smem + stage*STAGE_FLOATS;
        const float* Bsb = Asb + 128*PAD;
        #pragma unroll
        for (int kk=0;kk<BK;kk+=8){
            wmma::fragment<wmma::matrix_a,16,16,8,wmma::precision::tf32,wmma::row_major> af[4];
            wmma::fragment<wmma::matrix_b,16,16,8,wmma::precision::tf32,wmma::col_major> bf[2];
            #pragma unroll
            for (int i=0;i<4;i++) wmma::load_matrix_sync(af[i], &Asb[(wm*64 + i*16)*PAD + kk], PAD);
            #pragma unroll
            for (int j=0;j<2;j++) wmma::load_matrix_sync(bf[j], &Bsb[(wn*32 + j*16)*PAD + kk], PAD);
            #pragma unroll
            for (int i=0;i<4;i++)
                #pragma unroll
                for (int j=0;j<2;j++)
                    wmma::mma_sync(acc[i][j], af[i], bf[j], acc[i][j]);
        }
        __syncthreads();
        stage ^= 1;
    }

    // epilogue: reuse smem as per-warp 16x20 staging buffers
    float* cbuf = smem + (size_t)wid*16*20;
    #pragma unroll
    for (int i=0;i<4;i++){
        #pragma unroll
        for (int j=0;j<2;j++){
            wmma::store_matrix_sync(cbuf, acc[i][j], 20, wmma::mem_row_major);
            __syncwarp();
            int r  = lane >> 1;
            int cq = (lane & 1) * 8;
            int m  = m0 + wm*64 + i*16 + r;
            if (m < Mv){
                int nb = n0 + wn*32 + j*16 + cq;
                float v[8];
                #pragma unroll
                for (int c=0;c<8;c++){
                    float x = cbuf[r*20 + cq + c];
                    if (bptr) x += bptr[nb+c];
                    v[c] = (EPI==1) ? gelu_exact(x) : x;
                }
                *(float4*)&C[(size_t)m*N + nb    ] = make_float4(v[0],v[1],v[2],v[3]);
                *(float4*)&C[(size_t)m*N + nb + 4] = make_float4(v[4],v[5],v[6],v[7]);
            }
            __syncwarp();
        }
    }
}

// ---------------- LayerNorm(x + y) * g + b ----------------
__global__ void __launch_bounds__(128) ln_add_kernel(
    const float* __restrict__ X, const float* __restrict__ Y,
    const float* __restrict__ g0, const float* __restrict__ b0,
    int l, float* __restrict__ out, const int* __restrict__ cntPtr)
{
    int gen = blockIdx.y;
    if ((int)blockIdx.x >= cntPtr[gen]) return;
    size_t row = (size_t)gen*SEG + blockIdx.x;
    const float* g  = g0 + (size_t)(gen*NL + l)*HD;
    const float* bb = b0 + (size_t)(gen*NL + l)*HD;
    int t = threadIdx.x;
    float4 v = ((const float4*)X)[row*128 + t];
    float4 y = ((const float4*)Y)[row*128 + t];
    v.x+=y.x; v.y+=y.y; v.z+=y.z; v.w+=y.w;
    float s  = v.x+v.y+v.z+v.w;
    float sq = v.x*v.x+v.y*v.y+v.z*v.z+v.w*v.w;
    __shared__ float red[8];
    #pragma unroll
    for (int off=16;off;off>>=1){
        s  += __shfl_down_sync(0xffffffffu,s,off);
        sq += __shfl_down_sync(0xffffffffu,sq,off);
    }
    int warp = t>>5, lane = t&31;
    if (lane==0){ red[warp]=s; red[warp+4]=sq; }
    __syncthreads();
    if (t==0){
        float S=red[0]+red[1]+red[2]+red[3];
        float Q=red[4]+red[5]+red[6]+red[7];
        float mean=S*(1.f/512.f);
        float var =Q*(1.f/512.f) - mean*mean;
        red[0]=mean; red[1]=rsqrtf(var + 1e-5f);
    }
    __syncthreads();
    float mean=red[0], rs=red[1];
    float4 gg=((const float4*)g)[t], bv=((const float4*)bb)[t];
    float4 o;
    o.x=(v.x-mean)*rs*gg.x+bv.x;
    o.y=(v.y-mean)*rs*gg.y+bv.y;
    o.z=(v.z-mean)*rs*gg.z+bv.z;
    o.w=(v.w-mean)*rs*gg.w+bv.w;
    ((float4*)out)[row*128+t]=o;
}

// ---------------- compaction ----------------
__global__ void build_index_kernel(const int* __restrict__ mt)
{
    if (threadIdx.x==0){ d_cnt[0]=0; d_cnt[1]=0; }
    __syncthreads();
    for (int b=threadIdx.x; b<BSZ; b+=blockDim.x){
        int m = mt[b];
        if (m==1){ int p=atomicAdd(&d_cnt[0],1); d_idx[0][p]=b; d_pos[0][b]=p; }
        else if (m==2){ int p=atomicAdd(&d_cnt[1],1); d_idx[1][p]=b; d_pos[1][b]=p; }
    }
}

__global__ void __launch_bounds__(128) gather_kernel(
    const float* __restrict__ img, const float* __restrict__ text)
{
    int gi = blockIdx.y;
    int c  = blockIdx.x;
    if (c >= d_cnt[gi]) return;
    int r = d_idx[gi][c];
    const float* src = gi ? text : img;
    const float* tgt = gi ? img  : text;
    int t = threadIdx.x;
    size_t drow = (size_t)gi*SEG + c;
    ((float4*)d_srcC)[drow*128+t] = ((const float4*)src)[(size_t)r*128+t];
    ((float4*)d_tgtC)[drow*128+t] = ((const float4*)tgt)[(size_t)r*128+t];
}

// ---------------- weight preprocessing ----------------
__global__ void transpose_wv_kernel(const float* __restrict__ qkv_w)
{
    __shared__ float tile[32][33];
    int bz = blockIdx.z;
    const float* src = qkv_w + (size_t)bz*3*HD*HD + (size_t)2*HD*HD;
    int j0 = blockIdx.y*32, k0 = blockIdx.x*32;
    int tx = threadIdx.x, ty = threadIdx.y;
    #pragma unroll
    for (int r=0;r<32;r+=8)
        tile[ty+r][tx] = src[(size_t)(j0+ty+r)*HD + k0+tx];
    __syncthreads();
    float* dst = d_wvT + (size_t)bz*HD*HD;
    #pragma unroll
    for (int r=0;r<32;r+=8)
        dst[(size_t)(k0+ty+r)*HD + j0+tx] = tile[tx][ty+r];
}

// bc[z][n] = ao_w[z][n,:] . bv[z] + ao_b[z][n]   — one warp per row
__global__ void __launch_bounds__(256) bc_kernel(const float* __restrict__ ao_w,
                          const float* __restrict__ ao_b,
                          const float* __restrict__ qkv_b)
{
    int z = blockIdx.x;
    int n = blockIdx.y*8 + (threadIdx.x>>5);
    int lane = threadIdx.x&31;
    const float* ao = ao_w + (size_t)z*HD*HD + (size_t)n*HD;
    const float* bv = qkv_b + (size_t)z*3*HD + 2*HD;
    float s=0.f;
    #pragma unroll
    for (int j=lane*4;j<HD;j+=128){
        float4 a = *(const float4*)&ao[j];
        float4 b = *(const float4*)&bv[j];
        s += a.x*b.x + a.y*b.y + a.z*b.z + a.w*b.w;
    }
    #pragma unroll
    for (int off=16;off;off>>=1) s += __shfl_down_sync(0xffffffffu,s,off);
    if (lane==0) d_bc[(size_t)z*HD+n] = s + ao_b[(size_t)z*HD+n];
}

// ---------------- tiny prior MLP (1 row) ----------------
__global__ void prior_mm_kernel(const float* __restrict__ x, const float* __restrict__ W,
                                const float* __restrict__ b, float* __restrict__ out,
                                int K, int N, int dogelu)
{
    int gw = (blockIdx.x*blockDim.x + threadIdx.x)>>5;
    int lane = threadIdx.x & 31;
    if (gw >= N) return;
    float s=0.f;
    for (int k=lane;k<K;k+=32) s += x[k]*W[(size_t)gw*K+k];
    #pragma unroll
    for (int off=16;off;off>>=1) s += __shfl_down_sync(0xffffffffu,s,off);
    if (lane==0){ s += b[gw]; out[gw] = dogelu ? gelu_exact(s) : s; }
}

// ---------------- final selection + residual blend ----------------
__global__ void __launch_bounds__(128) final_kernel(
    const float* __restrict__ img, const float* __restrict__ text,
    const int* __restrict__ mtA, const float* __restrict__ rw,
    float* __restrict__ out)
{
    int b = blockIdx.x, t = threadIdx.x;
    int mt = mtA[b];
    float4 iv = ((const float4*)img )[(size_t)b*128+t];
    float4 tv = ((const float4*)text)[(size_t)b*128+t];
    float4 oi = iv, ot = tv;
    if (mt==3){
        oi = ((const float4*)d_prior)[t];
        ot = ((const float4*)d_prior)[128+t];
    } else if (mt==2){
        float r = rw[1], q = 1.f - r;
        float4 gv = ((const float4*)d_genb)[((size_t)SEG + d_pos[1][b])*128+t];
        oi.x=r*iv.x+q*gv.x; oi.y=r*iv.y+q*gv.y; oi.z=r*iv.z+q*gv.z; oi.w=r*iv.w+q*gv.w;
    } else if (mt==1){
        float r = rw[0], q = 1.f - r;
        float4 gv = ((const float4*)d_genb)[(size_t)d_pos[0][b]*128+t];
        ot.x=r*tv.x+q*gv.x; ot.y=r*tv.y+q*gv.y; ot.z=r*tv.z+q*gv.z; ot.w=r*tv.w+q*gv.w;
    }
    ((float4*)out)[(size_t)b*128+t] = oi;
    ((float4*)out)[(size_t)BSZ*128 + (size_t)b*128+t] = ot;
}

// ---------------- host orchestration ----------------
extern "C" void kernel_launch(void* const* d_in, const int* in_sizes, int n_in,
                              void* d_out, int out_size)
{
    const float* img  = (const float*)d_in[0];
    const float* text = (const float*)d_in[1];
    const float* ipw  = (const float*)d_in[2];
    const float* ipb  = (const float*)d_in[3];
    const float* qkvw = (const float*)d_in[4];
    const float* qkvb = (const float*)d_in[5];
    const float* aow  = (const float*)d_in[6];
    const float* aob  = (const float*)d_in[7];
    const float* ln1g = (const float*)d_in[8];
    const float* ln1b = (const float*)d_in[9];
    const float* ln2g = (const float*)d_in[10];
    const float* ln2b = (const float*)d_in[11];
    const float* f1w  = (const float*)d_in[12];
    const float* f1b  = (const float*)d_in[13];
    const float* f2w  = (const float*)d_in[14];
    const float* f2b  = (const float*)d_in[15];
    const float* opw  = (const float*)d_in[16];
    const float* opb  = (const float*)d_in[17];
    const float* rw   = (const float*)d_in[18];
    const float* pw1  = (const float*)d_in[19];
    const float* pb1  = (const float*)d_in[20];
    const float* pw2  = (const float*)d_in[21];
    const float* pb2  = (const float*)d_in[22];
    const float* pemb = (const float*)d_in[23];
    const int*   mt   = (const int*)d_in[24];
    float* out = (float*)d_out;

    static int smem_set = 0;
    if (!smem_set){
        cudaFuncSetAttribute(mm_tf32<0>, cudaFuncAttributeMaxDynamicSharedMemorySize, SMEM_BYTES);
        cudaFuncSetAttribute(mm_tf32<1>, cudaFuncAttributeMaxDynamicSharedMemorySize, SMEM_BYTES);
        smem_set = 1;
    }

    void* p;
    cudaGetSymbolAddress(&p, d_Wc);      float* Wc   = (float*)p;
    cudaGetSymbolAddress(&p, d_wvT);     float* wvT  = (float*)p;
    cudaGetSymbolAddress(&p, d_bc);      float* bc   = (float*)p;
    cudaGetSymbolAddress(&p, d_cnt);     int*   cnt  = (int*)p;
    cudaGetSymbolAddress(&p, d_srcC);    float* srcC = (float*)p;
    cudaGetSymbolAddress(&p, d_tgtC);    float* tgtC = (float*)p;
    cudaGetSymbolAddress(&p, d_xbuf);    float* xb   = (float*)p;
    cudaGetSymbolAddress(&p, d_t1);      float* t1   = (float*)p;
    cudaGetSymbolAddress(&p, d_hbuf);    float* hb   = (float*)p;
    cudaGetSymbolAddress(&p, d_genb);    float* genb = (float*)p;
    cudaGetSymbolAddress(&p, d_prior_h); float* ph   = (float*)p;
    cudaGetSymbolAddress(&p, d_prior);   float* pr   = (float*)p;

    const size_t HH   = (size_t)HD*HD;
    const size_t SH   = (size_t)SEG*HD;
    const size_t SH4  = (size_t)SEG*HD4;

    // 1) compaction + weight prep + prior
    build_index_kernel<<<1,256>>>(mt);
    transpose_wv_kernel<<<dim3(16,16,6), dim3(32,8)>>>(qkvw);
    mm_tf32<0><<<dim3(HD/BN, HD/BM, 6), 256, SMEM_BYTES>>>(
        aow, HH, wvT, HH, nullptr, 0, Wc, HH, HD, HD, HD, nullptr);
    bc_kernel<<<dim3(6,64),256>>>(aow, aob, qkvb);
    prior_mm_kernel<<<128,256>>>(pemb, pw1, pb1, ph, HD,   2*HD, 1);
    prior_mm_kernel<<<128,256>>>(ph,   pw2, pb2, pr, 2*HD, 2*HD, 0);

    // 2) both generators batched over z=2 on compacted rows
    gather_kernel<<<dim3(BSZ,2),128>>>(img, text);

    const dim3 gN512 (HD /BN, BSZ/BM, 2);
    const dim3 gN2048(HD4/BN, BSZ/BM, 2);
    const dim3 gLN   (BSZ, 2);

    mm_tf32<0><<<gN512,256,SMEM_BYTES>>>(srcC, SH, ipw, HH, ipb, HD, xb, SH, HD, HD, 0, cnt);
    for (int l=0;l<NL;l++){
        mm_tf32<0><<<gN512,256,SMEM_BYTES>>>(tgtC, SH, Wc + (size_t)l*HH, (size_t)NL*HH,
                                  bc + (size_t)l*HD, (size_t)NL*HD, t1, SH, HD, HD, 0, cnt);
        ln_add_kernel<<<gLN,128>>>(xb, t1, ln1g, ln1b, l, xb, cnt);
        mm_tf32<1><<<gN2048,256,SMEM_BYTES>>>(xb, SH, f1w + (size_t)l*HD4*HD, (size_t)NL*HD4*HD,
                                   f1b + (size_t)l*HD4, (size_t)NL*HD4, hb, SH4, HD4, HD, 0, cnt);
        mm_tf32<0><<<gN512,256,SMEM_BYTES>>>(hb, SH4, f2w + (size_t)l*HD*HD4, (size_t)NL*HD*HD4,
                                  f2b + (size_t)l*HD, (size_t)NL*HD, t1, SH, HD, HD4, 0, cnt);
        ln_add_kernel<<<gLN,128>>>(xb, t1, ln2g, ln2b, l, xb, cnt);
    }
    mm_tf32<0><<<gN512,256,SMEM_BYTES>>>(xb, SH, opw, HH, opb, HD, genb, SH, HD, HD, 0, cnt);

    // 3) final selection/blend
    final_kernel<<<BSZ,128>>>(img, text, mt, rw, out);
}

// round 5
// speedup vs baseline: 4.2102x; 2.1340x over previous
#include <cuda_runtime.h>
#include <math.h>
#include <cstdint>
#include <stdint.h>

#define BSZ 16384
#define HD 512
#define NL 3
#define HD4 2048
#define SEG BSZ

#define BM 128
#define BN 128
#define BK 32
#define PAD 36                       // smem row stride in floats
#define STAGE_FLOATS (2*128*PAD)     // A+B tiles for one stage
#define SMEM_BYTES (2*STAGE_FLOATS*4)

// ---------------- scratch ----------------
__device__ float d_Wc[6*HD*HD];
__device__ float d_wvT[6*HD*HD];
__device__ float d_bc[6*HD];
__device__ int   d_cnt[2];
__device__ int   d_idx[2][BSZ];
__device__ int   d_pos[2][BSZ];
__device__ float d_srcC[(size_t)2*SEG*HD];
__device__ float d_tgtC[(size_t)2*SEG*HD];
__device__ float d_xbuf[(size_t)2*SEG*HD];
__device__ float d_t1  [(size_t)2*SEG*HD];
__device__ float d_hbuf[(size_t)2*SEG*HD4];
__device__ float d_genb[(size_t)2*SEG*HD];
__device__ float d_prior_h[2*HD];
__device__ float d_prior  [2*HD];

__device__ __forceinline__ float gelu_exact(float x){
    return 0.5f*x*(1.0f+erff(x*0.70710678118654752440f));
}

__device__ __forceinline__ void cpasync16(unsigned int s, const void* g){
    asm volatile("cp.async.cg.shared.global [%0], [%1], 16;\n" :: "r"(s), "l"(g));
}
__device__ __forceinline__ void cpasync_commit(){
    asm volatile("cp.async.commit_group;\n");
}
__device__ __forceinline__ void ldsm_x4(unsigned int a, unsigned int &r0, unsigned int &r1,
                                        unsigned int &r2, unsigned int &r3){
    asm volatile("ldmatrix.sync.aligned.m8n8.x4.shared.b16 {%0,%1,%2,%3}, [%4];"
                 : "=r"(r0),"=r"(r1),"=r"(r2),"=r"(r3) : "r"(a));
}
__device__ __forceinline__ void mma_tf32(float* d, const unsigned int* a, const unsigned int* b){
    asm volatile(
        "mma.sync.aligned.m16n8k8.row.col.f32.tf32.tf32.f32 "
        "{%0,%1,%2,%3}, {%4,%5,%6,%7}, {%8,%9}, {%0,%1,%2,%3};"
        : "+f"(d[0]),"+f"(d[1]),"+f"(d[2]),"+f"(d[3])
        : "r"(a[0]),"r"(a[1]),"r"(a[2]),"r"(a[3]),"r"(b[0]),"r"(b[1]));
}

// ---------------- TF32 tensor-core GEMM: mma.sync + ldmatrix, cp.async 2-stage ----------------
// C[z][M,N] = A[z][M,K] @ W[z][N,K]^T + bias[z][N]
template<int EPI>
__global__ void __launch_bounds__(256, 2) mm_tf32(
    const float* __restrict__ A, size_t As_,
    const float* __restrict__ W, size_t Ws_,
    const float* __restrict__ bias, size_t bs_,
    float* __restrict__ C, size_t Cs_,
    int N, int K, int Mstatic, const int* __restrict__ cnt)
{
    const int z  = blockIdx.z;
    const int Mv = cnt ? cnt[z] : Mstatic;
    const int m0 = blockIdx.y * BM;
    if (m0 >= Mv) return;
    const int n0 = blockIdx.x * BN;
    A += (size_t)z * As_;
    W += (size_t)z * Ws_;
    C += (size_t)z * Cs_;
    const float* bptr = bias ? (bias + (size_t)z * bs_) : nullptr;

    extern __shared__ float smem[];
    const unsigned int smem_u32 = (unsigned int)__cvta_generic_to_shared(smem);

    const int tid  = threadIdx.x;
    const int wid  = tid >> 5;
    const int lane = tid & 31;
    const int wm   = wid & 1;    // 2 warp-rows of 64
    const int wn   = wid >> 1;   // 4 warp-cols of 32

    // ldmatrix per-thread address components
    const int arow = (lane & 7) + ((lane >> 3) & 1) * 8;   // A: matrix row within m16
    const int acol = ((lane >> 4) & 1) * 4;                // A: k-half
    const int brow = (lane & 7) + ((lane >> 4) & 1) * 8;   // B: n within n16 pair
    const int bcol = ((lane >> 3) & 1) * 4;                // B: k-half

    unsigned int a_off[4], b_off[2];
    #pragma unroll
    for (int i=0;i<4;i++) a_off[i] = (unsigned int)(((wm*64 + i*16 + arow)*PAD + acol)*4);
    #pragma unroll
    for (int p=0;p<2;p++) b_off[p] = (unsigned int)((128*PAD + (wn*32 + p*16 + brow)*PAD + bcol)*4);

    float acc[4][4][4];
    #pragma unroll
    for (int i=0;i<4;i++)
        #pragma unroll
        for (int j=0;j<4;j++)
            #pragma unroll
            for (int r=0;r<4;r++) acc[i][j][r]=0.f;

    auto load_stage = [&](int s, int k0){
        const unsigned int base = smem_u32 + (unsigned int)(s*STAGE_FLOATS*4);
        #pragma unroll
        for (int it=0; it<4; it++){
            int c  = tid + it*256;
            int r  = c >> 3;
            int kq = (c & 7) * 4;
            unsigned int off = (unsigned int)((r*PAD + kq)*4);
            cpasync16(base + off,                              &A[(size_t)(m0+r)*K + k0 + kq]);
            cpasync16(base + (unsigned int)(128*PAD*4) + off,  &W[(size_t)(n0+r)*K + k0 + kq]);
        }
        cpasync_commit();
    };

    load_stage(0, 0);
    int stage = 0;
    for (int k0=0; k0<K; k0+=BK){
        if (k0 + BK < K){
            load_stage(stage^1, k0+BK);
            asm volatile("cp.async.wait_group 1;\n");
        } else {
            asm volatile("cp.async.wait_group 0;\n");
        }
        __syncthreads();

        const unsigned int sb = smem_u32 + (unsigned int)(stage*STAGE_FLOATS*4);
        #pragma unroll
        for (int kk=0; kk<BK; kk+=8){
            unsigned int a[4][4], b[4][2];
            #pragma unroll
            for (int i=0;i<4;i++)
                ldsm_x4(sb + a_off[i] + (unsigned int)(kk*4), a[i][0],a[i][1],a[i][2],a[i][3]);
            #pragma unroll
            for (int p=0;p<2;p++)
                ldsm_x4(sb + b_off[p] + (unsigned int)(kk*4),
                        b[2*p][0], b[2*p][1], b[2*p+1][0], b[2*p+1][1]);
            #pragma unroll
            for (int i=0;i<4;i++)
                #pragma unroll
                for (int j=0;j<4;j++)
                    mma_tf32(acc[i][j], a[i], b[j]);
        }
        __syncthreads();
        stage ^= 1;
    }

    // epilogue: direct float2 stores (acc reg r: c0=(g,2t), c1=(g,2t+1), c2=(g+8,2t), c3=(g+8,2t+1))
    const int g   = lane >> 2;
    const int tig = lane & 3;
    float bj0[4], bj1[4];
    #pragma unroll
    for (int j=0;j<4;j++){
        int col = n0 + wn*32 + j*8 + 2*tig;
        bj0[j] = bptr ? bptr[col]   : 0.f;
        bj1[j] = bptr ? bptr[col+1] : 0.f;
    }
    #pragma unroll
    for (int i=0;i<4;i++){
        int row0 = m0 + wm*64 + i*16 + g;
        int row1 = row0 + 8;
        #pragma unroll
        for (int j=0;j<4;j++){
            int col = n0 + wn*32 + j*8 + 2*tig;
            if (row0 < Mv){
                float v0 = acc[i][j][0] + bj0[j];
                float v1 = acc[i][j][1] + bj1[j];
                if (EPI==1){ v0=gelu_exact(v0); v1=gelu_exact(v1); }
                *(float2*)&C[(size_t)row0*N + col] = make_float2(v0,v1);
            }
            if (row1 < Mv){
                float v2 = acc[i][j][2] + bj0[j];
                float v3 = acc[i][j][3] + bj1[j];
                if (EPI==1){ v2=gelu_exact(v2); v3=gelu_exact(v3); }
                *(float2*)&C[(size_t)row1*N + col] = make_float2(v2,v3);
            }
        }
    }
}

// ---------------- LayerNorm(x + y) * g + b ----------------
__global__ void __launch_bounds__(128) ln_add_kernel(
    const float* __restrict__ X, const float* __restrict__ Y,
    const float* __restrict__ g0, const float* __restrict__ b0,
    int l, float* __restrict__ out, const int* __restrict__ cntPtr)
{
    int gen = blockIdx.y;
    if ((int)blockIdx.x >= cntPtr[gen]) return;
    size_t row = (size_t)gen*SEG + blockIdx.x;
    const float* g  = g0 + (size_t)(gen*NL + l)*HD;
    const float* bb = b0 + (size_t)(gen*NL + l)*HD;
    int t = threadIdx.x;
    float4 v = ((const float4*)X)[row*128 + t];
    float4 y = ((const float4*)Y)[row*128 + t];
    v.x+=y.x; v.y+=y.y; v.z+=y.z; v.w+=y.w;
    float s  = v.x+v.y+v.z+v.w;
    float sq = v.x*v.x+v.y*v.y+v.z*v.z+v.w*v.w;
    __shared__ float red[8];
    #pragma unroll
    for (int off=16;off;off>>=1){
        s  += __shfl_down_sync(0xffffffffu,s,off);
        sq += __shfl_down_sync(0xffffffffu,sq,off);
    }
    int warp = t>>5, lane = t&31;
    if (lane==0){ red[warp]=s; red[warp+4]=sq; }
    __syncthreads();
    if (t==0){
        float S=red[0]+red[1]+red[2]+red[3];
        float Q=red[4]+red[5]+red[6]+red[7];
        float mean=S*(1.f/512.f);
        float var =Q*(1.f/512.f) - mean*mean;
        red[0]=mean; red[1]=rsqrtf(var + 1e-5f);
    }
    __syncthreads();
    float mean=red[0], rs=red[1];
    float4 gg=((const float4*)g)[t], bv=((const float4*)bb)[t];
    float4 o;
    o.x=(v.x-mean)*rs*gg.x+bv.x;
    o.y=(v.y-mean)*rs*gg.y+bv.y;
    o.z=(v.z-mean)*rs*gg.z+bv.z;
    o.w=(v.w-mean)*rs*gg.w+bv.w;
    ((float4*)out)[row*128+t]=o;
}

// ---------------- compaction ----------------
__global__ void build_index_kernel(const int* __restrict__ mt)
{
    if (threadIdx.x==0){ d_cnt[0]=0; d_cnt[1]=0; }
    __syncthreads();
    for (int b=threadIdx.x; b<BSZ; b+=blockDim.x){
        int m = mt[b];
        if (m==1){ int p=atomicAdd(&d_cnt[0],1); d_idx[0][p]=b; d_pos[0][b]=p; }
        else if (m==2){ int p=atomicAdd(&d_cnt[1],1); d_idx[1][p]=b; d_pos[1][b]=p; }
    }
}

__global__ void __launch_bounds__(128) gather_kernel(
    const float* __restrict__ img, const float* __restrict__ text)
{
    int gi = blockIdx.y;
    int c  = blockIdx.x;
    if (c >= d_cnt[gi]) return;
    int r = d_idx[gi][c];
    const float* src = gi ? text : img;
    const float* tgt = gi ? img  : text;
    int t = threadIdx.x;
    size_t drow = (size_t)gi*SEG + c;
    ((float4*)d_srcC)[drow*128+t] = ((const float4*)src)[(size_t)r*128+t];
    ((float4*)d_tgtC)[drow*128+t] = ((const float4*)tgt)[(size_t)r*128+t];
}

// ---------------- weight preprocessing ----------------
__global__ void transpose_wv_kernel(const float* __restrict__ qkv_w)
{
    __shared__ float tile[32][33];
    int bz = blockIdx.z;
    const float* src = qkv_w + (size_t)bz*3*HD*HD + (size_t)2*HD*HD;
    int j0 = blockIdx.y*32, k0 = blockIdx.x*32;
    int tx = threadIdx.x, ty = threadIdx.y;
    #pragma unroll
    for (int r=0;r<32;r+=8)
        tile[ty+r][tx] = src[(size_t)(j0+ty+r)*HD + k0+tx];
    __syncthreads();
    float* dst = d_wvT + (size_t)bz*HD*HD;
    #pragma unroll
    for (int r=0;r<32;r+=8)
        dst[(size_t)(k0+ty+r)*HD + j0+tx] = tile[tx][ty+r];
}

// bc[z][n] = ao_w[z][n,:] . bv[z] + ao_b[z][n]
__global__ void __launch_bounds__(256) bc_kernel(const float* __restrict__ ao_w,
                          const float* __restrict__ ao_b,
                          const float* __restrict__ qkv_b)
{
    int z = blockIdx.x;
    int n = blockIdx.y*8 + (threadIdx.x>>5);
    int lane = threadIdx.x&31;
    const float* ao = ao_w + (size_t)z*HD*HD + (size_t)n*HD;
    const float* bv = qkv_b + (size_t)z*3*HD + 2*HD;
    float s=0.f;
    #pragma unroll
    for (int j=lane*4;j<HD;j+=128){
        float4 a = *(const float4*)&ao[j];
        float4 b = *(const float4*)&bv[j];
        s += a.x*b.x + a.y*b.y + a.z*b.z + a.w*b.w;
    }
    #pragma unroll
    for (int off=16;off;off>>=1) s += __shfl_down_sync(0xffffffffu,s,off);
    if (lane==0) d_bc[(size_t)z*HD+n] = s + ao_b[(size_t)z*HD+n];
}

// ---------------- tiny prior MLP (1 row) ----------------
__global__ void prior_mm_kernel(const float* __restrict__ x, const float* __restrict__ W,
                                const float* __restrict__ b, float* __restrict__ out,
                                int K, int N, int dogelu)
{
    int gw = (blockIdx.x*blockDim.x + threadIdx.x)>>5;
    int lane = threadIdx.x & 31;
    if (gw >= N) return;
    float s=0.f;
    for (int k=lane;k<K;k+=32) s += x[k]*W[(size_t)gw*K+k];
    #pragma unroll
    for (int off=16;off;off>>=1) s += __shfl_down_sync(0xffffffffu,s,off);
    if (lane==0){ s += b[gw]; out[gw] = dogelu ? gelu_exact(s) : s; }
}

// ---------------- final selection + residual blend ----------------
__global__ void __launch_bounds__(128) final_kernel(
    const float* __restrict__ img, const float* __restrict__ text,
    const int* __restrict__ mtA, const float* __restrict__ rw,
    float* __restrict__ out)
{
    int b = blockIdx.x, t = threadIdx.x;
    int mt = mtA[b];
    float4 iv = ((const float4*)img )[(size_t)b*128+t];
    float4 tv = ((const float4*)text)[(size_t)b*128+t];
    float4 oi = iv, ot = tv;
    if (mt==3){
        oi = ((const float4*)d_prior)[t];
        ot = ((const float4*)d_prior)[128+t];
    } else if (mt==2){
        float r = rw[1], q = 1.f - r;
        float4 gv = ((const float4*)d_genb)[((size_t)SEG + d_pos[1][b])*128+t];
        oi.x=r*iv.x+q*gv.x; oi.y=r*iv.y+q*gv.y; oi.z=r*iv.z+q*gv.z; oi.w=r*iv.w+q*gv.w;
    } else if (mt==1){
        float r = rw[0], q = 1.f - r;
        float4 gv = ((const float4*)d_genb)[(size_t)d_pos[0][b]*128+t];
        ot.x=r*tv.x+q*gv.x; ot.y=r*tv.y+q*gv.y; ot.z=r*tv.z+q*gv.z; ot.w=r*tv.w+q*gv.w;
    }
    ((float4*)out)[(size_t)b*128+t] = oi;
    ((float4*)out)[(size_t)BSZ*128 + (size_t)b*128+t] = ot;
}

// ---------------- host orchestration ----------------
extern "C" void kernel_launch(void* const* d_in, const int* in_sizes, int n_in,
                              void* d_out, int out_size)
{
    const float* img  = (const float*)d_in[0];
    const float* text = (const float*)d_in[1];
    const float* ipw  = (const float*)d_in[2];
    const float* ipb  = (const float*)d_in[3];
    const float* qkvw = (const float*)d_in[4];
    const float* qkvb = (const float*)d_in[5];
    const float* aow  = (const float*)d_in[6];
    const float* aob  = (const float*)d_in[7];
    const float* ln1g = (const float*)d_in[8];
    const float* ln1b = (const float*)d_in[9];
    const float* ln2g = (const float*)d_in[10];
    const float* ln2b = (const float*)d_in[11];
    const float* f1w  = (const float*)d_in[12];
    const float* f1b  = (const float*)d_in[13];
    const float* f2w  = (const float*)d_in[14];
    const float* f2b  = (const float*)d_in[15];
    const float* opw  = (const float*)d_in[16];
    const float* opb  = (const float*)d_in[17];
    const float* rw   = (const float*)d_in[18];
    const float* pw1  = (const float*)d_in[19];
    const float* pb1  = (const float*)d_in[20];
    const float* pw2  = (const float*)d_in[21];
    const float* pb2  = (const float*)d_in[22];
    const float* pemb = (const float*)d_in[23];
    const int*   mt   = (const int*)d_in[24];
    float* out = (float*)d_out;

    static int smem_set = 0;
    if (!smem_set){
        cudaFuncSetAttribute(mm_tf32<0>, cudaFuncAttributeMaxDynamicSharedMemorySize, SMEM_BYTES);
        cudaFuncSetAttribute(mm_tf32<1>, cudaFuncAttributeMaxDynamicSharedMemorySize, SMEM_BYTES);
        smem_set = 1;
    }

    void* p;
    cudaGetSymbolAddress(&p, d_Wc);      float* Wc   = (float*)p;
    cudaGetSymbolAddress(&p, d_wvT);     float* wvT  = (float*)p;
    cudaGetSymbolAddress(&p, d_bc);      float* bc   = (float*)p;
    cudaGetSymbolAddress(&p, d_cnt);     int*   cnt  = (int*)p;
    cudaGetSymbolAddress(&p, d_srcC);    float* srcC = (float*)p;
    cudaGetSymbolAddress(&p, d_tgtC);    float* tgtC = (float*)p;
    cudaGetSymbolAddress(&p, d_xbuf);    float* xb   = (float*)p;
    cudaGetSymbolAddress(&p, d_t1);      float* t1   = (float*)p;
    cudaGetSymbolAddress(&p, d_hbuf);    float* hb   = (float*)p;
    cudaGetSymbolAddress(&p, d_genb);    float* genb = (float*)p;
    cudaGetSymbolAddress(&p, d_prior_h); float* ph   = (float*)p;
    cudaGetSymbolAddress(&p, d_prior);   float* pr   = (float*)p;

    const size_t HH   = (size_t)HD*HD;
    const size_t SH   = (size_t)SEG*HD;
    const size_t SH4  = (size_t)SEG*HD4;

    // 1) compaction + weight prep + prior
    build_index_kernel<<<1,256>>>(mt);
    transpose_wv_kernel<<<dim3(16,16,6), dim3(32,8)>>>(qkvw);
    mm_tf32<0><<<dim3(HD/BN, HD/BM, 6), 256, SMEM_BYTES>>>(
        aow, HH, wvT, HH, nullptr, 0, Wc, HH, HD, HD, HD, nullptr);
    bc_kernel<<<dim3(6,64),256>>>(aow, aob, qkvb);
    prior_mm_kernel<<<128,256>>>(pemb, pw1, pb1, ph, HD,   2*HD, 1);
    prior_mm_kernel<<<128,256>>>(ph,   pw2, pb2, pr, 2*HD, 2*HD, 0);

    // 2) both generators batched over z=2 on compacted rows
    gather_kernel<<<dim3(BSZ,2),128>>>(img, text);

    const dim3 gN512 (HD /BN, BSZ/BM, 2);
    const dim3 gN2048(HD4/BN, BSZ/BM, 2);
    const dim3 gLN   (BSZ, 2);

    mm_tf32<0><<<gN512,256,SMEM_BYTES>>>(srcC, SH, ipw, HH, ipb, HD, xb, SH, HD, HD, 0, cnt);
    for (int l=0;l<NL;l++){
        mm_tf32<0><<<gN512,256,SMEM_BYTES>>>(tgtC, SH, Wc + (size_t)l*HH, (size_t)NL*HH,
                                  bc + (size_t)l*HD, (size_t)NL*HD, t1, SH, HD, HD, 0, cnt);
        ln_add_kernel<<<gLN,128>>>(xb, t1, ln1g, ln1b, l, xb, cnt);
        mm_tf32<1><<<gN2048,256,SMEM_BYTES>>>(xb, SH, f1w + (size_t)l*HD4*HD, (size_t)NL*HD4*HD,
                                   f1b + (size_t)l*HD4, (size_t)NL*HD4, hb, SH4, HD4, HD, 0, cnt);
        mm_tf32<0><<<gN512,256,SMEM_BYTES>>>(hb, SH4, f2w + (size_t)l*HD*HD4, (size_t)NL*HD*HD4,
                                  f2b + (size_t)l*HD, (size_t)NL*HD, t1, SH, HD, HD4, 0, cnt);
        ln_add_kernel<<<gLN,128>>>(xb, t1, ln2g, ln2b, l, xb, cnt);
    }
    mm_tf32<0><<<gN512,256,SMEM_BYTES>>>(xb, SH, opw, HH, opb, HD, genb, SH, HD, HD, 0, cnt);

    // 3) final selection/blend
    final_kernel<<<BSZ,128>>>(img, text, mt, rw, out);
}

// round 6
// speedup vs baseline: 4.2540x; 1.0104x over previous
#include <cuda_runtime.h>
#include <math.h>
#include <cstdint>
#include <stdint.h>

#define BSZ 16384
#define HD 512
#define NL 3
#define HD4 2048
#define SEG BSZ

#define BM 128
#define BN 128
#define BK 32
#define PAD 36
#define STAGE_FLOATS (2*128*PAD)
#define SMEM_BYTES (2*STAGE_FLOATS*4)

// fused GEMM+LN tile: 64 x 512 (full row per CTA)
#define BMF 64
#define STF ((BMF+HD)*PAD)            // floats per stage
#define SMEM_LN_BYTES (2*STF*4)

// ---------------- scratch ----------------
__device__ float d_Wc[6*HD*HD];
__device__ float d_wvT[6*HD*HD];
__device__ float d_bc[6*HD];
__device__ int   d_cnt[2];
__device__ int   d_idx[2][BSZ];
__device__ int   d_pos[2][BSZ];
__device__ float d_srcC[(size_t)2*SEG*HD];
__device__ float d_tgtC[(size_t)2*SEG*HD];
__device__ float d_xbuf[(size_t)2*SEG*HD];
__device__ float d_hbuf[(size_t)2*SEG*HD4];
__device__ float d_genb[(size_t)2*SEG*HD];
__device__ float d_prior_h[2*HD];
__device__ float d_prior  [2*HD];

__device__ __forceinline__ float gelu_exact(float x){
    return 0.5f*x*(1.0f+erff(x*0.70710678118654752440f));
}

__device__ __forceinline__ void cpasync16(unsigned int s, const void* g){
    asm volatile("cp.async.cg.shared.global [%0], [%1], 16;\n" :: "r"(s), "l"(g));
}
__device__ __forceinline__ void cpasync_commit(){
    asm volatile("cp.async.commit_group;\n");
}
__device__ __forceinline__ void ldsm_x4(unsigned int a, unsigned int &r0, unsigned int &r1,
                                        unsigned int &r2, unsigned int &r3){
    asm volatile("ldmatrix.sync.aligned.m8n8.x4.shared.b16 {%0,%1,%2,%3}, [%4];"
                 : "=r"(r0),"=r"(r1),"=r"(r2),"=r"(r3) : "r"(a));
}
__device__ __forceinline__ void mma_tf32(float* d, const unsigned int* a, const unsigned int* b){
    asm volatile(
        "mma.sync.aligned.m16n8k8.row.col.f32.tf32.tf32.f32 "
        "{%0,%1,%2,%3}, {%4,%5,%6,%7}, {%8,%9}, {%0,%1,%2,%3};"
        : "+f"(d[0]),"+f"(d[1]),"+f"(d[2]),"+f"(d[3])
        : "r"(a[0]),"r"(a[1]),"r"(a[2]),"r"(a[3]),"r"(b[0]),"r"(b[1]));
}

// ---------------- standard TF32 GEMM (mma.sync + ldmatrix, 2-stage cp.async) ----------------
// C[z][M,N] = A[z][M,K] @ W[z][N,K]^T + bias[z][N]
template<int EPI>
__global__ void __launch_bounds__(256, 2) mm_tf32(
    const float* __restrict__ A, size_t As_,
    const float* __restrict__ W, size_t Ws_,
    const float* __restrict__ bias, size_t bs_,
    float* __restrict__ C, size_t Cs_,
    int N, int K, int Mstatic, const int* __restrict__ cnt)
{
    const int z  = blockIdx.z;
    const int Mv = cnt ? cnt[z] : Mstatic;
    const int m0 = blockIdx.y * BM;
    if (m0 >= Mv) return;
    const int n0 = blockIdx.x * BN;
    A += (size_t)z * As_;
    W += (size_t)z * Ws_;
    C += (size_t)z * Cs_;
    const float* bptr = bias ? (bias + (size_t)z * bs_) : nullptr;

    extern __shared__ float smem[];
    const unsigned int smem_u32 = (unsigned int)__cvta_generic_to_shared(smem);

    const int tid  = threadIdx.x;
    const int wid  = tid >> 5;
    const int lane = tid & 31;
    const int wm   = wid & 1;
    const int wn   = wid >> 1;

    const int arow = (lane & 7) + ((lane >> 3) & 1) * 8;
    const int acol = ((lane >> 4) & 1) * 4;
    const int brow = (lane & 7) + ((lane >> 4) & 1) * 8;
    const int bcol = ((lane >> 3) & 1) * 4;

    unsigned int a_off[4], b_off[2];
    #pragma unroll
    for (int i=0;i<4;i++) a_off[i] = (unsigned int)(((wm*64 + i*16 + arow)*PAD + acol)*4);
    #pragma unroll
    for (int p=0;p<2;p++) b_off[p] = (unsigned int)((128*PAD + (wn*32 + p*16 + brow)*PAD + bcol)*4);

    float acc[4][4][4];
    #pragma unroll
    for (int i=0;i<4;i++)
        #pragma unroll
        for (int j=0;j<4;j++)
            #pragma unroll
            for (int r=0;r<4;r++) acc[i][j][r]=0.f;

    auto load_stage = [&](int s, int k0){
        const unsigned int base = smem_u32 + (unsigned int)(s*STAGE_FLOATS*4);
        #pragma unroll
        for (int it=0; it<4; it++){
            int c  = tid + it*256;
            int r  = c >> 3;
            int kq = (c & 7) * 4;
            unsigned int off = (unsigned int)((r*PAD + kq)*4);
            cpasync16(base + off,                              &A[(size_t)(m0+r)*K + k0 + kq]);
            cpasync16(base + (unsigned int)(128*PAD*4) + off,  &W[(size_t)(n0+r)*K + k0 + kq]);
        }
        cpasync_commit();
    };

    load_stage(0, 0);
    int stage = 0;
    for (int k0=0; k0<K; k0+=BK){
        if (k0 + BK < K){
            load_stage(stage^1, k0+BK);
            asm volatile("cp.async.wait_group 1;\n");
        } else {
            asm volatile("cp.async.wait_group 0;\n");
        }
        __syncthreads();

        const unsigned int sb = smem_u32 + (unsigned int)(stage*STAGE_FLOATS*4);
        #pragma unroll
        for (int kk=0; kk<BK; kk+=8){
            unsigned int a[4][4], b[4][2];
            #pragma unroll
            for (int i=0;i<4;i++)
                ldsm_x4(sb + a_off[i] + (unsigned int)(kk*4), a[i][0],a[i][1],a[i][2],a[i][3]);
            #pragma unroll
            for (int p=0;p<2;p++)
                ldsm_x4(sb + b_off[p] + (unsigned int)(kk*4),
                        b[2*p][0], b[2*p][1], b[2*p+1][0], b[2*p+1][1]);
            #pragma unroll
            for (int i=0;i<4;i++)
                #pragma unroll
                for (int j=0;j<4;j++)
                    mma_tf32(acc[i][j], a[i], b[j]);
        }
        __syncthreads();
        stage ^= 1;
    }

    const int g   = lane >> 2;
    const int tig = lane & 3;
    #pragma unroll
    for (int i=0;i<4;i++){
        int row0 = m0 + wm*64 + i*16 + g;
        int row1 = row0 + 8;
        #pragma unroll
        for (int j=0;j<4;j++){
            int col = n0 + wn*32 + j*8 + 2*tig;
            float b0 = bptr ? bptr[col]   : 0.f;
            float b1 = bptr ? bptr[col+1] : 0.f;
            if (row0 < Mv){
                float v0 = acc[i][j][0] + b0;
                float v1 = acc[i][j][1] + b1;
                if (EPI==1){ v0=gelu_exact(v0); v1=gelu_exact(v1); }
                *(float2*)&C[(size_t)row0*N + col] = make_float2(v0,v1);
            }
            if (row1 < Mv){
                float v2 = acc[i][j][2] + b0;
                float v3 = acc[i][j][3] + b1;
                if (EPI==1){ v2=gelu_exact(v2); v3=gelu_exact(v3); }
                *(float2*)&C[(size_t)row1*N + col] = make_float2(v2,v3);
            }
        }
    }
}

// ---------------- fused GEMM + residual + LayerNorm, N = HD = 512 ----------------
// Out[z][m,:] = LayerNorm( Xres[z][m,:] + A[z][m,:]@W[z]^T + bias[z] ) * lng + lnb
__global__ void __launch_bounds__(256, 1) mm_ln(
    const float* __restrict__ A, size_t As_,
    const float* __restrict__ W, size_t Ws_,
    const float* __restrict__ bias, size_t bs_,
    const float* __restrict__ Xres, size_t Xs_,
    const float* __restrict__ lng, const float* __restrict__ lnb, size_t lns_,
    float* __restrict__ Out, size_t Os_,
    int K, const int* __restrict__ cnt)
{
    const int z  = blockIdx.z;
    const int Mv = cnt[z];
    const int m0 = blockIdx.y * BMF;
    if (m0 >= Mv) return;
    A    += (size_t)z * As_;
    W    += (size_t)z * Ws_;
    Xres += (size_t)z * Xs_;
    Out  += (size_t)z * Os_;
    const float* bptr = bias + (size_t)z * bs_;
    const float* gptr = lng  + (size_t)z * lns_;
    const float* hptr = lnb  + (size_t)z * lns_;

    extern __shared__ float smem[];
    const unsigned int smem_u32 = (unsigned int)__cvta_generic_to_shared(smem);

    const int tid  = threadIdx.x;
    const int wid  = tid >> 5;
    const int lane = tid & 31;
    const int wm   = wid & 1;     // 2 m-halves of 32
    const int wn   = wid >> 1;    // 4 n-quarters of 128

    const int arow = (lane & 7) + ((lane >> 3) & 1) * 8;
    const int acol = ((lane >> 4) & 1) * 4;
    const int brow = (lane & 7) + ((lane >> 4) & 1) * 8;
    const int bcol = ((lane >> 3) & 1) * 4;

    unsigned int a_off[2], b_off[8];
    #pragma unroll
    for (int i=0;i<2;i++) a_off[i] = (unsigned int)(((wm*32 + i*16 + arow)*PAD + acol)*4);
    #pragma unroll
    for (int p=0;p<8;p++) b_off[p] = (unsigned int)((BMF*PAD + (wn*128 + p*16 + brow)*PAD + bcol)*4);

    float acc[2][16][4];
    #pragma unroll
    for (int i=0;i<2;i++)
        #pragma unroll
        for (int j=0;j<16;j++)
            #pragma unroll
            for (int r=0;r<4;r++) acc[i][j][r]=0.f;

    auto load_stage = [&](int s, int k0){
        const unsigned int base = smem_u32 + (unsigned int)(s*STF*4);
        #pragma unroll
        for (int it=0; it<2; it++){
            int c  = tid + it*256;
            int r  = c >> 3;
            int kq = (c & 7) * 4;
            cpasync16(base + (unsigned int)((r*PAD + kq)*4), &A[(size_t)(m0+r)*K + k0 + kq]);
        }
        #pragma unroll
        for (int it=0; it<16; it++){
            int c  = tid + it*256;
            int r  = c >> 3;                  // 0..511 (full N)
            int kq = (c & 7) * 4;
            cpasync16(base + (unsigned int)((BMF*PAD + r*PAD + kq)*4), &W[(size_t)r*K + k0 + kq]);
        }
        cpasync_commit();
    };

    load_stage(0, 0);
    int stage = 0;
    for (int k0=0; k0<K; k0+=BK){
        if (k0 + BK < K){
            load_stage(stage^1, k0+BK);
            asm volatile("cp.async.wait_group 1;\n");
        } else {
            asm volatile("cp.async.wait_group 0;\n");
        }
        __syncthreads();

        const unsigned int sb = smem_u32 + (unsigned int)(stage*STF*4);
        #pragma unroll
        for (int kk=0; kk<BK; kk+=8){
            unsigned int a[2][4], b[16][2];
            #pragma unroll
            for (int i=0;i<2;i++)
                ldsm_x4(sb + a_off[i] + (unsigned int)(kk*4), a[i][0],a[i][1],a[i][2],a[i][3]);
            #pragma unroll
            for (int p=0;p<8;p++)
                ldsm_x4(sb + b_off[p] + (unsigned int)(kk*4),
                        b[2*p][0], b[2*p][1], b[2*p+1][0], b[2*p+1][1]);
            #pragma unroll
            for (int i=0;i<2;i++)
                #pragma unroll
                for (int j=0;j<16;j++)
                    mma_tf32(acc[i][j], a[i], b[j]);
        }
        __syncthreads();
        stage ^= 1;
    }

    // ---- fold bias + residual into acc ----
    const int g   = lane >> 2;
    const int tig = lane & 3;
    #pragma unroll
    for (int i=0;i<2;i++){
        int row0 = m0 + wm*32 + i*16 + g;
        int row1 = row0 + 8;
        #pragma unroll
        for (int j=0;j<16;j++){
            int col = wn*128 + j*8 + 2*tig;
            float b0 = bptr[col], b1 = bptr[col+1];
            if (row0 < Mv){
                float2 x = *(const float2*)&Xres[(size_t)row0*HD + col];
                acc[i][j][0] += b0 + x.x;
                acc[i][j][1] += b1 + x.y;
            }
            if (row1 < Mv){
                float2 x = *(const float2*)&Xres[(size_t)row1*HD + col];
                acc[i][j][2] += b0 + x.x;
                acc[i][j][3] += b1 + x.y;
            }
        }
    }

    // ---- per-row stats: sum over this thread's 32 cols, reduce 4 lanes, then 4 warps ----
    float S[2][2], Q[2][2];
    #pragma unroll
    for (int i=0;i<2;i++)
        #pragma unroll
        for (int h=0;h<2;h++){
            float s=0.f, q=0.f;
            #pragma unroll
            for (int j=0;j<16;j++){
                float v0=acc[i][j][2*h], v1=acc[i][j][2*h+1];
                s += v0+v1; q += v0*v0+v1*v1;
            }
            s += __shfl_xor_sync(0xffffffffu, s, 1);
            s += __shfl_xor_sync(0xffffffffu, s, 2);
            q += __shfl_xor_sync(0xffffffffu, q, 1);
            q += __shfl_xor_sync(0xffffffffu, q, 2);
            S[i][h]=s; Q[i][h]=q;
        }
    float* redS = smem;          // [64][4]
    float* redQ = smem + 256;    // [64][4]
    if (tig==0){
        #pragma unroll
        for (int i=0;i<2;i++)
            #pragma unroll
            for (int h=0;h<2;h++){
                int lr = wm*32 + i*16 + g + h*8;
                redS[lr*4+wn] = S[i][h];
                redQ[lr*4+wn] = Q[i][h];
            }
    }
    __syncthreads();

    // ---- normalize + store ----
    #pragma unroll
    for (int i=0;i<2;i++){
        #pragma unroll
        for (int h=0;h<2;h++){
            int lr  = wm*32 + i*16 + g + h*8;
            int row = m0 + lr;
            if (row >= Mv) continue;
            float s = redS[lr*4+0]+redS[lr*4+1]+redS[lr*4+2]+redS[lr*4+3];
            float q = redQ[lr*4+0]+redQ[lr*4+1]+redQ[lr*4+2]+redQ[lr*4+3];
            float mean = s*(1.f/512.f);
            float var  = q*(1.f/512.f) - mean*mean;
            float rs   = rsqrtf(var + 1e-5f);
            #pragma unroll
            for (int j=0;j<16;j++){
                int col = wn*128 + j*8 + 2*tig;
                float g0=gptr[col], g1=gptr[col+1], h0=hptr[col], h1=hptr[col+1];
                float v0=(acc[i][j][2*h  ]-mean)*rs*g0+h0;
                float v1=(acc[i][j][2*h+1]-mean)*rs*g1+h1;
                *(float2*)&Out[(size_t)row*HD + col] = make_float2(v0,v1);
            }
        }
    }
}

// ---------------- compaction ----------------
__global__ void build_index_kernel(const int* __restrict__ mt)
{
    if (threadIdx.x==0){ d_cnt[0]=0; d_cnt[1]=0; }
    __syncthreads();
    for (int b=threadIdx.x; b<BSZ; b+=blockDim.x){
        int m = mt[b];
        if (m==1){ int p=atomicAdd(&d_cnt[0],1); d_idx[0][p]=b; d_pos[0][b]=p; }
        else if (m==2){ int p=atomicAdd(&d_cnt[1],1); d_idx[1][p]=b; d_pos[1][b]=p; }
    }
}

__global__ void __launch_bounds__(128) gather_kernel(
    const float* __restrict__ img, const float* __restrict__ text)
{
    int gi = blockIdx.y;
    int c  = blockIdx.x;
    if (c >= d_cnt[gi]) return;
    int r = d_idx[gi][c];
    const float* src = gi ? text : img;
    const float* tgt = gi ? img  : text;
    int t = threadIdx.x;
    size_t drow = (size_t)gi*SEG + c;
    ((float4*)d_srcC)[drow*128+t] = ((const float4*)src)[(size_t)r*128+t];
    ((float4*)d_tgtC)[drow*128+t] = ((const float4*)tgt)[(size_t)r*128+t];
}

// ---------------- weight preprocessing ----------------
__global__ void transpose_wv_kernel(const float* __restrict__ qkv_w)
{
    __shared__ float tile[32][33];
    int bz = blockIdx.z;
    const float* src = qkv_w + (size_t)bz*3*HD*HD + (size_t)2*HD*HD;
    int j0 = blockIdx.y*32, k0 = blockIdx.x*32;
    int tx = threadIdx.x, ty = threadIdx.y;
    #pragma unroll
    for (int r=0;r<32;r+=8)
        tile[ty+r][tx] = src[(size_t)(j0+ty+r)*HD + k0+tx];
    __syncthreads();
    float* dst = d_wvT + (size_t)bz*HD*HD;
    #pragma unroll
    for (int r=0;r<32;r+=8)
        dst[(size_t)(k0+ty+r)*HD + j0+tx] = tile[tx][ty+r];
}

__global__ void __launch_bounds__(256) bc_kernel(const float* __restrict__ ao_w,
                          const float* __restrict__ ao_b,
                          const float* __restrict__ qkv_b)
{
    int z = blockIdx.x;
    int n = blockIdx.y*8 + (threadIdx.x>>5);
    int lane = threadIdx.x&31;
    const float* ao = ao_w + (size_t)z*HD*HD + (size_t)n*HD;
    const float* bv = qkv_b + (size_t)z*3*HD + 2*HD;
    float s=0.f;
    #pragma unroll
    for (int j=lane*4;j<HD;j+=128){
        float4 a = *(const float4*)&ao[j];
        float4 b = *(const float4*)&bv[j];
        s += a.x*b.x + a.y*b.y + a.z*b.z + a.w*b.w;
    }
    #pragma unroll
    for (int off=16;off;off>>=1) s += __shfl_down_sync(0xffffffffu,s,off);
    if (lane==0) d_bc[(size_t)z*HD+n] = s + ao_b[(size_t)z*HD+n];
}

// ---------------- tiny prior MLP (1 row) ----------------
__global__ void prior_mm_kernel(const float* __restrict__ x, const float* __restrict__ W,
                                const float* __restrict__ b, float* __restrict__ out,
                                int K, int N, int dogelu)
{
    int gw = (blockIdx.x*blockDim.x + threadIdx.x)>>5;
    int lane = threadIdx.x & 31;
    if (gw >= N) return;
    float s=0.f;
    for (int k=lane;k<K;k+=32) s += x[k]*W[(size_t)gw*K+k];
    #pragma unroll
    for (int off=16;off;off>>=1) s += __shfl_down_sync(0xffffffffu,s,off);
    if (lane==0){ s += b[gw]; out[gw] = dogelu ? gelu_exact(s) : s; }
}

// ---------------- final selection + residual blend ----------------
__global__ void __launch_bounds__(128) final_kernel(
    const float* __restrict__ img, const float* __restrict__ text,
    const int* __restrict__ mtA, const float* __restrict__ rw,
    float* __restrict__ out)
{
    int b = blockIdx.x, t = threadIdx.x;
    int mt = mtA[b];
    float4 iv = ((const float4*)img )[(size_t)b*128+t];
    float4 tv = ((const float4*)text)[(size_t)b*128+t];
    float4 oi = iv, ot = tv;
    if (mt==3){
        oi = ((const float4*)d_prior)[t];
        ot = ((const float4*)d_prior)[128+t];
    } else if (mt==2){
        float r = rw[1], q = 1.f - r;
        float4 gv = ((const float4*)d_genb)[((size_t)SEG + d_pos[1][b])*128+t];
        oi.x=r*iv.x+q*gv.x; oi.y=r*iv.y+q*gv.y; oi.z=r*iv.z+q*gv.z; oi.w=r*iv.w+q*gv.w;
    } else if (mt==1){
        float r = rw[0], q = 1.f - r;
        float4 gv = ((const float4*)d_genb)[(size_t)d_pos[0][b]*128+t];
        ot.x=r*tv.x+q*gv.x; ot.y=r*tv.y+q*gv.y; ot.z=r*tv.z+q*gv.z; ot.w=r*tv.w+q*gv.w;
    }
    ((float4*)out)[(size_t)b*128+t] = oi;
    ((float4*)out)[(size_t)BSZ*128 + (size_t)b*128+t] = ot;
}

// ---------------- host orchestration ----------------
extern "C" void kernel_launch(void* const* d_in, const int* in_sizes, int n_in,
                              void* d_out, int out_size)
{
    const float* img  = (const float*)d_in[0];
    const float* text = (const float*)d_in[1];
    const float* ipw  = (const float*)d_in[2];
    const float* ipb  = (const float*)d_in[3];
    const float* qkvw = (const float*)d_in[4];
    const float* qkvb = (const float*)d_in[5];
    const float* aow  = (const float*)d_in[6];
    const float* aob  = (const float*)d_in[7];
    const float* ln1g = (const float*)d_in[8];
    const float* ln1b = (const float*)d_in[9];
    const float* ln2g = (const float*)d_in[10];
    const float* ln2b = (const float*)d_in[11];
    const float* f1w  = (const float*)d_in[12];
    const float* f1b  = (const float*)d_in[13];
    const float* f2w  = (const float*)d_in[14];
    const float* f2b  = (const float*)d_in[15];
    const float* opw  = (const float*)d_in[16];
    const float* opb  = (const float*)d_in[17];
    const float* rw   = (const float*)d_in[18];
    const float* pw1  = (const float*)d_in[19];
    const float* pb1  = (const float*)d_in[20];
    const float* pw2  = (const float*)d_in[21];
    const float* pb2  = (const float*)d_in[22];
    const float* pemb = (const float*)d_in[23];
    const int*   mt   = (const int*)d_in[24];
    float* out = (float*)d_out;

    static int smem_set = 0;
    if (!smem_set){
        cudaFuncSetAttribute(mm_tf32<0>, cudaFuncAttributeMaxDynamicSharedMemorySize, SMEM_BYTES);
        cudaFuncSetAttribute(mm_tf32<1>, cudaFuncAttributeMaxDynamicSharedMemorySize, SMEM_BYTES);
        cudaFuncSetAttribute(mm_ln,      cudaFuncAttributeMaxDynamicSharedMemorySize, SMEM_LN_BYTES);
        smem_set = 1;
    }

    void* p;
    cudaGetSymbolAddress(&p, d_Wc);      float* Wc   = (float*)p;
    cudaGetSymbolAddress(&p, d_wvT);     float* wvT  = (float*)p;
    cudaGetSymbolAddress(&p, d_bc);      float* bc   = (float*)p;
    cudaGetSymbolAddress(&p, d_cnt);     int*   cnt  = (int*)p;
    cudaGetSymbolAddress(&p, d_srcC);    float* srcC = (float*)p;
    cudaGetSymbolAddress(&p, d_tgtC);    float* tgtC = (float*)p;
    cudaGetSymbolAddress(&p, d_xbuf);    float* xb   = (float*)p;
    cudaGetSymbolAddress(&p, d_hbuf);    float* hb   = (float*)p;
    cudaGetSymbolAddress(&p, d_genb);    float* genb = (float*)p;
    cudaGetSymbolAddress(&p, d_prior_h); float* ph   = (float*)p;
    cudaGetSymbolAddress(&p, d_prior);   float* pr   = (float*)p;

    const size_t HH   = (size_t)HD*HD;
    const size_t SH   = (size_t)SEG*HD;
    const size_t SH4  = (size_t)SEG*HD4;

    // 1) compaction + weight prep + prior
    build_index_kernel<<<1,256>>>(mt);
    transpose_wv_kernel<<<dim3(16,16,6), dim3(32,8)>>>(qkvw);
    mm_tf32<0><<<dim3(HD/BN, HD/BM, 6), 256, SMEM_BYTES>>>(
        aow, HH, wvT, HH, nullptr, 0, Wc, HH, HD, HD, HD, nullptr);
    bc_kernel<<<dim3(6,64),256>>>(aow, aob, qkvb);
    prior_mm_kernel<<<128,256>>>(pemb, pw1, pb1, ph, HD,   2*HD, 1);
    prior_mm_kernel<<<128,256>>>(ph,   pw2, pb2, pr, 2*HD, 2*HD, 0);

    // 2) both generators batched over z=2 on compacted rows
    gather_kernel<<<dim3(BSZ,2),128>>>(img, text);

    const dim3 gN512 (HD /BN, BSZ/BM, 2);
    const dim3 gN2048(HD4/BN, BSZ/BM, 2);
    const dim3 gLN   (1, BSZ/BMF, 2);

    // x = srcC @ ipw.T + ipb
    mm_tf32<0><<<gN512,256,SMEM_BYTES>>>(srcC, SH, ipw, HH, ipb, HD, xb, SH, HD, HD, 0, cnt);
    for (int l=0;l<NL;l++){
        // x = LN1( x + tgtC @ Wc[l].T + bc[l] )
        mm_ln<<<gLN,256,SMEM_LN_BYTES>>>(tgtC, SH, Wc + (size_t)l*HH, (size_t)NL*HH,
                                  bc + (size_t)l*HD, (size_t)NL*HD,
                                  xb, SH,
                                  ln1g + (size_t)l*HD, ln1b + (size_t)l*HD, (size_t)NL*HD,
                                  xb, SH, HD, cnt);
        // h = gelu(x @ f1w.T + f1b)
        mm_tf32<1><<<gN2048,256,SMEM_BYTES>>>(xb, SH, f1w + (size_t)l*HD4*HD, (size_t)NL*HD4*HD,
                                   f1b + (size_t)l*HD4, (size_t)NL*HD4, hb, SH4, HD4, HD, 0, cnt);
        // x = LN2( x + h @ f2w.T + f2b )
        mm_ln<<<gLN,256,SMEM_LN_BYTES>>>(hb, SH4, f2w + (size_t)l*HD*HD4, (size_t)NL*HD*HD4,
                                  f2b + (size_t)l*HD, (size_t)NL*HD,
                                  xb, SH,
                                  ln2g + (size_t)l*HD, ln2b + (size_t)l*HD, (size_t)NL*HD,
                                  xb, SH, HD4, cnt);
    }
    // gen core = x @ opw.T + opb
    mm_tf32<0><<<gN512,256,SMEM_BYTES>>>(xb, SH, opw, HH, opb, HD, genb, SH, HD, HD, 0, cnt);

    // 3) final selection/blend
    final_kernel<<<BSZ,128>>>(img, text, mt, rw, out);
}

// round 7
// speedup vs baseline: 6.4604x; 1.5187x over previous
#include <cuda_runtime.h>
#include <cuda_bf16.h>
#include <math.h>
#include <cstdint>
#include <stdint.h>

#define BSZ 16384
#define HD 512
#define NL 3
#define HD4 2048
#define SEG BSZ

// bf16 GEMM tiles
#define BM 128
#define BN 128
#define BK 64                         // elements
#define PADE 72                       // smem row stride in bf16 elements (144B)
#define STAGE_EL ((BM+BN)*PADE)       // elements per stage
#define SMEM16_BYTES (2*STAGE_EL*2)

// fused GEMM+LN tile: 64 x 512
#define BMF 64
#define STF_EL ((BMF+HD)*PADE)
#define SMEM_LN_BYTES (2*STF_EL*2)

// ---------------- scratch ----------------
__device__ float d_bc[6*HD];
__device__ int   d_cnt[2];
__device__ int   d_idx[2][BSZ];
__device__ int   d_pos[2][BSZ];
__device__ float d_xbuf[(size_t)2*SEG*HD];
__device__ float d_genb[(size_t)2*SEG*HD];
__device__ float d_prior_h[2*HD];
__device__ float d_prior  [2*HD];

__device__ __align__(16) __nv_bfloat16 d_srcC16[(size_t)2*SEG*HD];
__device__ __align__(16) __nv_bfloat16 d_tgtC16[(size_t)2*SEG*HD];
__device__ __align__(16) __nv_bfloat16 d_x16  [(size_t)2*SEG*HD];
__device__ __align__(16) __nv_bfloat16 d_hb16 [(size_t)2*SEG*HD4];
__device__ __align__(16) __nv_bfloat16 d_aow16[(size_t)6*HD*HD];
__device__ __align__(16) __nv_bfloat16 d_wvT16[(size_t)6*HD*HD];
__device__ __align__(16) __nv_bfloat16 d_Wc16 [(size_t)6*HD*HD];
__device__ __align__(16) __nv_bfloat16 d_ipw16[(size_t)2*HD*HD];
__device__ __align__(16) __nv_bfloat16 d_opw16[(size_t)2*HD*HD];
__device__ __align__(16) __nv_bfloat16 d_f1w16[(size_t)6*HD4*HD];
__device__ __align__(16) __nv_bfloat16 d_f2w16[(size_t)6*HD*HD4];

__device__ __forceinline__ float gelu_exact(float x){
    return 0.5f*x*(1.0f+erff(x*0.70710678118654752440f));
}
__device__ __forceinline__ void cpasync16(unsigned int s, const void* g){
    asm volatile("cp.async.cg.shared.global [%0], [%1], 16;\n" :: "r"(s), "l"(g));
}
__device__ __forceinline__ void cpasync_commit(){
    asm volatile("cp.async.commit_group;\n");
}
__device__ __forceinline__ void ldsm_x4(unsigned int a, unsigned int &r0, unsigned int &r1,
                                        unsigned int &r2, unsigned int &r3){
    asm volatile("ldmatrix.sync.aligned.m8n8.x4.shared.b16 {%0,%1,%2,%3}, [%4];"
                 : "=r"(r0),"=r"(r1),"=r"(r2),"=r"(r3) : "r"(a));
}
__device__ __forceinline__ void mma_bf16(float* d, const unsigned int* a, const unsigned int* b){
    asm volatile(
        "mma.sync.aligned.m16n8k16.row.col.f32.bf16.bf16.f32 "
        "{%0,%1,%2,%3}, {%4,%5,%6,%7}, {%8,%9}, {%0,%1,%2,%3};"
        : "+f"(d[0]),"+f"(d[1]),"+f"(d[2]),"+f"(d[3])
        : "r"(a[0]),"r"(a[1]),"r"(a[2]),"r"(a[3]),"r"(b[0]),"r"(b[1]));
}
__device__ __forceinline__ unsigned int packbf(float a, float b){
    __nv_bfloat162 p; p.x = __float2bfloat16_rn(a); p.y = __float2bfloat16_rn(b);
    return *reinterpret_cast<unsigned int*>(&p);
}

// ---------------- bf16 GEMM: C[z][M,N] = A[z]@W[z]^T + bias ----------------
// EPI: 0 none, 1 gelu.  OUTM: 0 fp32 only, 1 fp32+bf16 shadow, 2 bf16 only.
template<int EPI, int OUTM>
__global__ void __launch_bounds__(256, 2) mm16(
    const __nv_bfloat16* __restrict__ A, size_t As_,
    const __nv_bfloat16* __restrict__ W, size_t Ws_,
    const float* __restrict__ bias, size_t bs_,
    float* __restrict__ C, __nv_bfloat16* __restrict__ C16, size_t Cs_,
    int N, int K, int Mstatic, const int* __restrict__ cnt)
{
    const int z  = blockIdx.z;
    const int Mv = cnt ? cnt[z] : Mstatic;
    const int m0 = blockIdx.y * BM;
    if (m0 >= Mv) return;
    const int n0 = blockIdx.x * BN;
    A += (size_t)z * As_;
    W += (size_t)z * Ws_;
    if (OUTM != 2) C   += (size_t)z * Cs_;
    if (OUTM != 0) C16 += (size_t)z * Cs_;
    const float* bptr = bias ? (bias + (size_t)z * bs_) : nullptr;

    extern __shared__ __nv_bfloat16 smem16[];
    const unsigned int smem_u32 = (unsigned int)__cvta_generic_to_shared(smem16);

    const int tid  = threadIdx.x;
    const int wid  = tid >> 5;
    const int lane = tid & 31;
    const int wm   = wid & 1;
    const int wn   = wid >> 1;

    const int arow = (lane & 7) + ((lane >> 3) & 1) * 8;
    const int acol = ((lane >> 4) & 1) * 8;
    const int brow = (lane & 7) + ((lane >> 4) & 1) * 8;
    const int bcol = ((lane >> 3) & 1) * 8;

    unsigned int a_off[4], b_off[2];
    #pragma unroll
    for (int i=0;i<4;i++) a_off[i] = (unsigned int)(((wm*64 + i*16 + arow)*PADE + acol)*2);
    #pragma unroll
    for (int p=0;p<2;p++) b_off[p] = (unsigned int)((BM*PADE + (wn*32 + p*16 + brow)*PADE + bcol)*2);

    float acc[4][4][4];
    #pragma unroll
    for (int i=0;i<4;i++)
        #pragma unroll
        for (int j=0;j<4;j++)
            #pragma unroll
            for (int r=0;r<4;r++) acc[i][j][r]=0.f;

    auto load_stage = [&](int s, int k0){
        const unsigned int base = smem_u32 + (unsigned int)(s*STAGE_EL*2);
        #pragma unroll
        for (int it=0; it<4; it++){
            int c  = tid + it*256;          // 0..1023
            int r  = c >> 3;                // 0..127
            int kq = (c & 7) * 8;           // element offset
            unsigned int off = (unsigned int)((r*PADE + kq)*2);
            cpasync16(base + off,                                &A[(size_t)(m0+r)*K + k0 + kq]);
            cpasync16(base + (unsigned int)(BM*PADE*2) + off,    &W[(size_t)(n0+r)*K + k0 + kq]);
        }
        cpasync_commit();
    };

    load_stage(0, 0);
    int stage = 0;
    for (int k0=0; k0<K; k0+=BK){
        if (k0 + BK < K){
            load_stage(stage^1, k0+BK);
            asm volatile("cp.async.wait_group 1;\n");
        } else {
            asm volatile("cp.async.wait_group 0;\n");
        }
        __syncthreads();

        const unsigned int sb = smem_u32 + (unsigned int)(stage*STAGE_EL*2);
        #pragma unroll
        for (int kk=0; kk<BK; kk+=16){
            unsigned int a[4][4], b[4][2];
            #pragma unroll
            for (int i=0;i<4;i++)
                ldsm_x4(sb + a_off[i] + (unsigned int)(kk*2), a[i][0],a[i][1],a[i][2],a[i][3]);
            #pragma unroll
            for (int p=0;p<2;p++)
                ldsm_x4(sb + b_off[p] + (unsigned int)(kk*2),
                        b[2*p][0], b[2*p][1], b[2*p+1][0], b[2*p+1][1]);
            #pragma unroll
            for (int i=0;i<4;i++)
                #pragma unroll
                for (int j=0;j<4;j++)
                    mma_bf16(acc[i][j], a[i], b[j]);
        }
        __syncthreads();
        stage ^= 1;
    }

    const int g   = lane >> 2;
    const int tig = lane & 3;
    #pragma unroll
    for (int i=0;i<4;i++){
        int row0 = m0 + wm*64 + i*16 + g;
        int row1 = row0 + 8;
        #pragma unroll
        for (int j=0;j<4;j++){
            int col = n0 + wn*32 + j*8 + 2*tig;
            float b0 = bptr ? bptr[col]   : 0.f;
            float b1 = bptr ? bptr[col+1] : 0.f;
            float v0 = acc[i][j][0] + b0, v1 = acc[i][j][1] + b1;
            float v2 = acc[i][j][2] + b0, v3 = acc[i][j][3] + b1;
            if (EPI==1){ v0=gelu_exact(v0); v1=gelu_exact(v1); v2=gelu_exact(v2); v3=gelu_exact(v3); }
            if (row0 < Mv){
                if (OUTM != 2) *(float2*)&C[(size_t)row0*N + col] = make_float2(v0,v1);
                if (OUTM != 0) *(unsigned int*)&C16[(size_t)row0*N + col] = packbf(v0,v1);
            }
            if (row1 < Mv){
                if (OUTM != 2) *(float2*)&C[(size_t)row1*N + col] = make_float2(v2,v3);
                if (OUTM != 0) *(unsigned int*)&C16[(size_t)row1*N + col] = packbf(v2,v3);
            }
        }
    }
}

// ---------------- fused bf16 GEMM + residual + LayerNorm (N = 512) ----------------
__global__ void __launch_bounds__(256, 1) mm16_ln(
    const __nv_bfloat16* __restrict__ A, size_t As_,
    const __nv_bfloat16* __restrict__ W, size_t Ws_,
    const float* __restrict__ bias, size_t bs_,
    const float* __restrict__ Xres, size_t Xs_,
    const float* __restrict__ lng, const float* __restrict__ lnb, size_t lns_,
    float* __restrict__ Out, __nv_bfloat16* __restrict__ Out16, size_t Os_,
    int K, const int* __restrict__ cnt)
{
    const int z  = blockIdx.z;
    const int Mv = cnt[z];
    const int m0 = blockIdx.y * BMF;
    if (m0 >= Mv) return;
    A     += (size_t)z * As_;
    W     += (size_t)z * Ws_;
    Xres  += (size_t)z * Xs_;
    Out   += (size_t)z * Os_;
    Out16 += (size_t)z * Os_;
    const float* bptr = bias + (size_t)z * bs_;
    const float* gptr = lng  + (size_t)z * lns_;
    const float* hptr = lnb  + (size_t)z * lns_;

    extern __shared__ __nv_bfloat16 smem16[];
    const unsigned int smem_u32 = (unsigned int)__cvta_generic_to_shared(smem16);
    float* smf = reinterpret_cast<float*>(smem16);

    const int tid  = threadIdx.x;
    const int wid  = tid >> 5;
    const int lane = tid & 31;
    const int wm   = wid & 1;     // 2 m-halves of 32
    const int wn   = wid >> 1;    // 4 n-quarters of 128

    const int arow = (lane & 7) + ((lane >> 3) & 1) * 8;
    const int acol = ((lane >> 4) & 1) * 8;
    const int brow = (lane & 7) + ((lane >> 4) & 1) * 8;
    const int bcol = ((lane >> 3) & 1) * 8;

    unsigned int a_off[2], b_off[8];
    #pragma unroll
    for (int i=0;i<2;i++) a_off[i] = (unsigned int)(((wm*32 + i*16 + arow)*PADE + acol)*2);
    #pragma unroll
    for (int p=0;p<8;p++) b_off[p] = (unsigned int)((BMF*PADE + (wn*128 + p*16 + brow)*PADE + bcol)*2);

    float acc[2][16][4];
    #pragma unroll
    for (int i=0;i<2;i++)
        #pragma unroll
        for (int j=0;j<16;j++)
            #pragma unroll
            for (int r=0;r<4;r++) acc[i][j][r]=0.f;

    auto load_stage = [&](int s, int k0){
        const unsigned int base = smem_u32 + (unsigned int)(s*STF_EL*2);
        #pragma unroll
        for (int it=0; it<2; it++){
            int c  = tid + it*256;          // 0..511
            int r  = c >> 3;                // 0..63
            int kq = (c & 7) * 8;
            cpasync16(base + (unsigned int)((r*PADE + kq)*2), &A[(size_t)(m0+r)*K + k0 + kq]);
        }
        #pragma unroll
        for (int it=0; it<16; it++){
            int c  = tid + it*256;          // 0..4095
            int r  = c >> 3;                // 0..511
            int kq = (c & 7) * 8;
            cpasync16(base + (unsigned int)((BMF*PADE + r*PADE + kq)*2), &W[(size_t)r*K + k0 + kq]);
        }
        cpasync_commit();
    };

    load_stage(0, 0);
    int stage = 0;
    for (int k0=0; k0<K; k0+=BK){
        if (k0 + BK < K){
            load_stage(stage^1, k0+BK);
            asm volatile("cp.async.wait_group 1;\n");
        } else {
            asm volatile("cp.async.wait_group 0;\n");
        }
        __syncthreads();

        const unsigned int sb = smem_u32 + (unsigned int)(stage*STF_EL*2);
        #pragma unroll
        for (int kk=0; kk<BK; kk+=16){
            unsigned int a[2][4], b[16][2];
            #pragma unroll
            for (int i=0;i<2;i++)
                ldsm_x4(sb + a_off[i] + (unsigned int)(kk*2), a[i][0],a[i][1],a[i][2],a[i][3]);
            #pragma unroll
            for (int p=0;p<8;p++)
                ldsm_x4(sb + b_off[p] + (unsigned int)(kk*2),
                        b[2*p][0], b[2*p][1], b[2*p+1][0], b[2*p+1][1]);
            #pragma unroll
            for (int i=0;i<2;i++)
                #pragma unroll
                for (int j=0;j<16;j++)
                    mma_bf16(acc[i][j], a[i], b[j]);
        }
        __syncthreads();
        stage ^= 1;
    }

    // ---- bias + residual into acc ----
    const int g   = lane >> 2;
    const int tig = lane & 3;
    #pragma unroll
    for (int i=0;i<2;i++){
        int row0 = m0 + wm*32 + i*16 + g;
        int row1 = row0 + 8;
        #pragma unroll
        for (int j=0;j<16;j++){
            int col = wn*128 + j*8 + 2*tig;
            float b0 = bptr[col], b1 = bptr[col+1];
            if (row0 < Mv){
                float2 x = *(const float2*)&Xres[(size_t)row0*HD + col];
                acc[i][j][0] += b0 + x.x;
                acc[i][j][1] += b1 + x.y;
            }
            if (row1 < Mv){
                float2 x = *(const float2*)&Xres[(size_t)row1*HD + col];
                acc[i][j][2] += b0 + x.x;
                acc[i][j][3] += b1 + x.y;
            }
        }
    }

    // ---- per-row stats ----
    float S[2][2], Q[2][2];
    #pragma unroll
    for (int i=0;i<2;i++)
        #pragma unroll
        for (int h=0;h<2;h++){
            float s=0.f, q=0.f;
            #pragma unroll
            for (int j=0;j<16;j++){
                float v0=acc[i][j][2*h], v1=acc[i][j][2*h+1];
                s += v0+v1; q += v0*v0+v1*v1;
            }
            s += __shfl_xor_sync(0xffffffffu, s, 1);
            s += __shfl_xor_sync(0xffffffffu, s, 2);
            q += __shfl_xor_sync(0xffffffffu, q, 1);
            q += __shfl_xor_sync(0xffffffffu, q, 2);
            S[i][h]=s; Q[i][h]=q;
        }
    float* redS = smf;          // [64][4]
    float* redQ = smf + 256;
    if (tig==0){
        #pragma unroll
        for (int i=0;i<2;i++)
            #pragma unroll
            for (int h=0;h<2;h++){
                int lr = wm*32 + i*16 + g + h*8;
                redS[lr*4+wn] = S[i][h];
                redQ[lr*4+wn] = Q[i][h];
            }
    }
    __syncthreads();

    // ---- normalize + dual store ----
    #pragma unroll
    for (int i=0;i<2;i++){
        #pragma unroll
        for (int h=0;h<2;h++){
            int lr  = wm*32 + i*16 + g + h*8;
            int row = m0 + lr;
            if (row >= Mv) continue;
            float s = redS[lr*4+0]+redS[lr*4+1]+redS[lr*4+2]+redS[lr*4+3];
            float q = redQ[lr*4+0]+redQ[lr*4+1]+redQ[lr*4+2]+redQ[lr*4+3];
            float mean = s*(1.f/512.f);
            float var  = q*(1.f/512.f) - mean*mean;
            float rs   = rsqrtf(var + 1e-5f);
            #pragma unroll
            for (int j=0;j<16;j++){
                int col = wn*128 + j*8 + 2*tig;
                float g0=gptr[col], g1=gptr[col+1], h0=hptr[col], h1=hptr[col+1];
                float v0=(acc[i][j][2*h  ]-mean)*rs*g0+h0;
                float v1=(acc[i][j][2*h+1]-mean)*rs*g1+h1;
                *(float2*)&Out[(size_t)row*HD + col] = make_float2(v0,v1);
                *(unsigned int*)&Out16[(size_t)row*HD + col] = packbf(v0,v1);
            }
        }
    }
}

// ---------------- helpers ----------------
__global__ void cvt_bf16_kernel(const float* __restrict__ src, __nv_bfloat16* __restrict__ dst, int n)
{
    int i = (blockIdx.x*blockDim.x + threadIdx.x)*4;
    if (i >= n) return;
    float4 v = *(const float4*)&src[i];
    unsigned int p0 = packbf(v.x, v.y);
    unsigned int p1 = packbf(v.z, v.w);
    *(uint2*)&dst[i] = make_uint2(p0, p1);
}

__global__ void build_index_kernel(const int* __restrict__ mt)
{
    if (threadIdx.x==0){ d_cnt[0]=0; d_cnt[1]=0; }
    __syncthreads();
    for (int b=threadIdx.x; b<BSZ; b+=blockDim.x){
        int m = mt[b];
        if (m==1){ int p=atomicAdd(&d_cnt[0],1); d_idx[0][p]=b; d_pos[0][b]=p; }
        else if (m==2){ int p=atomicAdd(&d_cnt[1],1); d_idx[1][p]=b; d_pos[1][b]=p; }
    }
}

__global__ void __launch_bounds__(128) gather_kernel(
    const float* __restrict__ img, const float* __restrict__ text)
{
    int gi = blockIdx.y;
    int c  = blockIdx.x;
    if (c >= d_cnt[gi]) return;
    int r = d_idx[gi][c];
    const float* src = gi ? text : img;
    const float* tgt = gi ? img  : text;
    int t = threadIdx.x;
    size_t drow = (size_t)gi*SEG + c;
    float4 sv = ((const float4*)src)[(size_t)r*128+t];
    float4 tv = ((const float4*)tgt)[(size_t)r*128+t];
    *(uint2*)&d_srcC16[drow*HD + t*4] = make_uint2(packbf(sv.x,sv.y), packbf(sv.z,sv.w));
    *(uint2*)&d_tgtC16[drow*HD + t*4] = make_uint2(packbf(tv.x,tv.y), packbf(tv.z,tv.w));
}

// transpose wv (rows 2H..3H of qkv_w[z]) into bf16 d_wvT16[z]
__global__ void transpose_wv_kernel(const float* __restrict__ qkv_w)
{
    __shared__ float tile[32][33];
    int bz = blockIdx.z;
    const float* src = qkv_w + (size_t)bz*3*HD*HD + (size_t)2*HD*HD;
    int j0 = blockIdx.y*32, k0 = blockIdx.x*32;
    int tx = threadIdx.x, ty = threadIdx.y;
    #pragma unroll
    for (int r=0;r<32;r+=8)
        tile[ty+r][tx] = src[(size_t)(j0+ty+r)*HD + k0+tx];
    __syncthreads();
    __nv_bfloat16* dst = d_wvT16 + (size_t)bz*HD*HD;
    #pragma unroll
    for (int r=0;r<32;r+=8)
        dst[(size_t)(k0+ty+r)*HD + j0+tx] = __float2bfloat16_rn(tile[tx][ty+r]);
}

__global__ void __launch_bounds__(256) bc_kernel(const float* __restrict__ ao_w,
                          const float* __restrict__ ao_b,
                          const float* __restrict__ qkv_b)
{
    int z = blockIdx.x;
    int n = blockIdx.y*8 + (threadIdx.x>>5);
    int lane = threadIdx.x&31;
    const float* ao = ao_w + (size_t)z*HD*HD + (size_t)n*HD;
    const float* bv = qkv_b + (size_t)z*3*HD + 2*HD;
    float s=0.f;
    #pragma unroll
    for (int j=lane*4;j<HD;j+=128){
        float4 a = *(const float4*)&ao[j];
        float4 b = *(const float4*)&bv[j];
        s += a.x*b.x + a.y*b.y + a.z*b.z + a.w*b.w;
    }
    #pragma unroll
    for (int off=16;off;off>>=1) s += __shfl_down_sync(0xffffffffu,s,off);
    if (lane==0) d_bc[(size_t)z*HD+n] = s + ao_b[(size_t)z*HD+n];
}

__global__ void prior_mm_kernel(const float* __restrict__ x, const float* __restrict__ W,
                                const float* __restrict__ b, float* __restrict__ out,
                                int K, int N, int dogelu)
{
    int gw = (blockIdx.x*blockDim.x + threadIdx.x)>>5;
    int lane = threadIdx.x & 31;
    if (gw >= N) return;
    float s=0.f;
    for (int k=lane;k<K;k+=32) s += x[k]*W[(size_t)gw*K+k];
    #pragma unroll
    for (int off=16;off;off>>=1) s += __shfl_down_sync(0xffffffffu,s,off);
    if (lane==0){ s += b[gw]; out[gw] = dogelu ? gelu_exact(s) : s; }
}

__global__ void __launch_bounds__(128) final_kernel(
    const float* __restrict__ img, const float* __restrict__ text,
    const int* __restrict__ mtA, const float* __restrict__ rw,
    float* __restrict__ out)
{
    int b = blockIdx.x, t = threadIdx.x;
    int mt = mtA[b];
    float4 iv = ((const float4*)img )[(size_t)b*128+t];
    float4 tv = ((const float4*)text)[(size_t)b*128+t];
    float4 oi = iv, ot = tv;
    if (mt==3){
        oi = ((const float4*)d_prior)[t];
        ot = ((const float4*)d_prior)[128+t];
    } else if (mt==2){
        float r = rw[1], q = 1.f - r;
        float4 gv = ((const float4*)d_genb)[((size_t)SEG + d_pos[1][b])*128+t];
        oi.x=r*iv.x+q*gv.x; oi.y=r*iv.y+q*gv.y; oi.z=r*iv.z+q*gv.z; oi.w=r*iv.w+q*gv.w;
    } else if (mt==1){
        float r = rw[0], q = 1.f - r;
        float4 gv = ((const float4*)d_genb)[(size_t)d_pos[0][b]*128+t];
        ot.x=r*tv.x+q*gv.x; ot.y=r*tv.y+q*gv.y; ot.z=r*tv.z+q*gv.z; ot.w=r*tv.w+q*gv.w;
    }
    ((float4*)out)[(size_t)b*128+t] = oi;
    ((float4*)out)[(size_t)BSZ*128 + (size_t)b*128+t] = ot;
}

// ---------------- host orchestration ----------------
extern "C" void kernel_launch(void* const* d_in, const int* in_sizes, int n_in,
                              void* d_out, int out_size)
{
    const float* img  = (const float*)d_in[0];
    const float* text = (const float*)d_in[1];
    const float* ipw  = (const float*)d_in[2];
    const float* ipb  = (const float*)d_in[3];
    const float* qkvw = (const float*)d_in[4];
    const float* qkvb = (const float*)d_in[5];
    const float* aow  = (const float*)d_in[6];
    const float* aob  = (const float*)d_in[7];
    const float* ln1g = (const float*)d_in[8];
    const float* ln1b = (const float*)d_in[9];
    const float* ln2g = (const float*)d_in[10];
    const float* ln2b = (const float*)d_in[11];
    const float* f1w  = (const float*)d_in[12];
    const float* f1b  = (const float*)d_in[13];
    const float* f2w  = (const float*)d_in[14];
    const float* f2b  = (const float*)d_in[15];
    const float* opw  = (const float*)d_in[16];
    const float* opb  = (const float*)d_in[17];
    const float* rw   = (const float*)d_in[18];
    const float* pw1  = (const float*)d_in[19];
    const float* pb1  = (const float*)d_in[20];
    const float* pw2  = (const float*)d_in[21];
    const float* pb2  = (const float*)d_in[22];
    const float* pemb = (const float*)d_in[23];
    const int*   mt   = (const int*)d_in[24];
    float* out = (float*)d_out;

    static int smem_set = 0;
    if (!smem_set){
        cudaFuncSetAttribute(mm16<0,0>, cudaFuncAttributeMaxDynamicSharedMemorySize, SMEM16_BYTES);
        cudaFuncSetAttribute(mm16<0,1>, cudaFuncAttributeMaxDynamicSharedMemorySize, SMEM16_BYTES);
        cudaFuncSetAttribute(mm16<0,2>, cudaFuncAttributeMaxDynamicSharedMemorySize, SMEM16_BYTES);
        cudaFuncSetAttribute(mm16<1,2>, cudaFuncAttributeMaxDynamicSharedMemorySize, SMEM16_BYTES);
        cudaFuncSetAttribute(mm16_ln,   cudaFuncAttributeMaxDynamicSharedMemorySize, SMEM_LN_BYTES);
        smem_set = 1;
    }

    void* p;
    cudaGetSymbolAddress(&p, d_bc);     float* bc   = (float*)p;
    cudaGetSymbolAddress(&p, d_cnt);    int*   cnt  = (int*)p;
    cudaGetSymbolAddress(&p, d_xbuf);   float* xb   = (float*)p;
    cudaGetSymbolAddress(&p, d_genb);   float* genb = (float*)p;
    cudaGetSymbolAddress(&p, d_prior_h);float* ph   = (float*)p;
    cudaGetSymbolAddress(&p, d_prior);  float* pr   = (float*)p;
    cudaGetSymbolAddress(&p, d_srcC16); __nv_bfloat16* srcC16 = (__nv_bfloat16*)p;
    cudaGetSymbolAddress(&p, d_tgtC16); __nv_bfloat16* tgtC16 = (__nv_bfloat16*)p;
    cudaGetSymbolAddress(&p, d_x16);    __nv_bfloat16* x16    = (__nv_bfloat16*)p;
    cudaGetSymbolAddress(&p, d_hb16);   __nv_bfloat16* hb16   = (__nv_bfloat16*)p;
    cudaGetSymbolAddress(&p, d_aow16);  __nv_bfloat16* aow16  = (__nv_bfloat16*)p;
    cudaGetSymbolAddress(&p, d_wvT16);  __nv_bfloat16* wvT16  = (__nv_bfloat16*)p;
    cudaGetSymbolAddress(&p, d_Wc16);   __nv_bfloat16* Wc16   = (__nv_bfloat16*)p;
    cudaGetSymbolAddress(&p, d_ipw16);  __nv_bfloat16* ipw16  = (__nv_bfloat16*)p;
    cudaGetSymbolAddress(&p, d_opw16);  __nv_bfloat16* opw16  = (__nv_bfloat16*)p;
    cudaGetSymbolAddress(&p, d_f1w16);  __nv_bfloat16* f1w16  = (__nv_bfloat16*)p;
    cudaGetSymbolAddress(&p, d_f2w16);  __nv_bfloat16* f2w16  = (__nv_bfloat16*)p;

    const size_t HH  = (size_t)HD*HD;
    const size_t SH  = (size_t)SEG*HD;
    const size_t SH4 = (size_t)SEG*HD4;

    auto cvt = [&](const float* s, __nv_bfloat16* d, size_t n){
        cvt_bf16_kernel<<<(unsigned)((n/4 + 255)/256), 256>>>(s, d, (int)n);
    };

    // 1) compaction + weight conversion + prep + prior
    build_index_kernel<<<1,256>>>(mt);
    cvt(aow, aow16, 6*HH);
    cvt(ipw, ipw16, 2*HH);
    cvt(opw, opw16, 2*HH);
    cvt(f1w, f1w16, (size_t)6*HD4*HD);
    cvt(f2w, f2w16, (size_t)6*HD*HD4);
    transpose_wv_kernel<<<dim3(16,16,6), dim3(32,8)>>>(qkvw);
    // Wc16[z] = aow16[z] @ wvT16[z]^T   (bf16 out only)
    mm16<0,2><<<dim3(HD/BN, HD/BM, 6), 256, SMEM16_BYTES>>>(
        aow16, HH, wvT16, HH, nullptr, 0, nullptr, Wc16, HH, HD, HD, HD, nullptr);
    bc_kernel<<<dim3(6,64),256>>>(aow, aob, qkvb);
    prior_mm_kernel<<<128,256>>>(pemb, pw1, pb1, ph, HD,   2*HD, 1);
    prior_mm_kernel<<<128,256>>>(ph,   pw2, pb2, pr, 2*HD, 2*HD, 0);

    // 2) both generators batched over z=2 on compacted rows
    gather_kernel<<<dim3(BSZ,2),128>>>(img, text);

    const dim3 gN512 (HD /BN, BSZ/BM, 2);
    const dim3 gN2048(HD4/BN, BSZ/BM, 2);
    const dim3 gLN   (1, BSZ/BMF, 2);

    // x = srcC @ ipw^T + ipb   (fp32 + bf16 shadow)
    mm16<0,1><<<gN512,256,SMEM16_BYTES>>>(srcC16, SH, ipw16, HH, ipb, HD,
                                          xb, x16, SH, HD, HD, 0, cnt);
    for (int l=0;l<NL;l++){
        // x = LN1( x + tgtC @ Wc[l]^T + bc[l] )
        mm16_ln<<<gLN,256,SMEM_LN_BYTES>>>(tgtC16, SH, Wc16 + (size_t)l*HH, (size_t)NL*HH,
                                  bc + (size_t)l*HD, (size_t)NL*HD,
                                  xb, SH,
                                  ln1g + (size_t)l*HD, ln1b + (size_t)l*HD, (size_t)NL*HD,
                                  xb, x16, SH, HD, cnt);
        // h = gelu(x @ f1w^T + f1b)   (bf16 only)
        mm16<1,2><<<gN2048,256,SMEM16_BYTES>>>(x16, SH, f1w16 + (size_t)l*HD4*HD, (size_t)NL*HD4*HD,
                                   f1b + (size_t)l*HD4, (size_t)NL*HD4,
                                   nullptr, hb16, SH4, HD4, HD, 0, cnt);
        // x = LN2( x + h @ f2w^T + f2b )
        mm16_ln<<<gLN,256,SMEM_LN_BYTES>>>(hb16, SH4, f2w16 + (size_t)l*HD*HD4, (size_t)NL*HD*HD4,
                                  f2b + (size_t)l*HD, (size_t)NL*HD,
                                  xb, SH,
                                  ln2g + (size_t)l*HD, ln2b + (size_t)l*HD, (size_t)NL*HD,
                                  xb, x16, SH, HD4, cnt);
    }
    // gen core = x @ opw^T + opb   (fp32 only)
    mm16<0,0><<<gN512,256,SMEM16_BYTES>>>(x16, SH, opw16, HH, opb, HD,
                                          genb, nullptr, SH, HD, HD, 0, cnt);

    // 3) final selection/blend
    final_kernel<<<BSZ,128>>>(img, text, mt, rw, out);
}

// round 10
// speedup vs baseline: 6.5689x; 1.0168x over previous
#include <cuda_runtime.h>
#include <cuda_bf16.h>
#include <math.h>
#include <cstdint>
#include <stdint.h>

#define BSZ 16384
#define HD 512
#define NL 3
#define HD4 2048
#define SEG BSZ

// bf16 GEMM tiles
#define BM 128
#define BN 128
#define BK 64                         // elements
#define PADE 72                       // smem row stride in bf16 elements (144B)
#define STAGE_EL ((BM+BN)*PADE)       // elements per stage
#define SMEM16_BYTES (3*STAGE_EL*2)   // 3-stage ring

// fused GEMM+LN tile: 64 x 512, 2-stage
#define BMF 64
#define STF_EL ((BMF+HD)*PADE)
#define SMEM_LN_BYTES (2*STF_EL*2)

// ---------------- scratch ----------------
__device__ float d_bc[6*HD];
__device__ int   d_cnt[2];
__device__ int   d_idx[2][BSZ];
__device__ int   d_pos[2][BSZ];
__device__ float d_xbuf[(size_t)2*SEG*HD];
__device__ float d_genb[(size_t)2*SEG*HD];
__device__ float d_prior_h[2*HD];
__device__ float d_prior  [2*HD];

__device__ __align__(16) __nv_bfloat16 d_srcC16[(size_t)2*SEG*HD];
__device__ __align__(16) __nv_bfloat16 d_tgtC16[(size_t)2*SEG*HD];
__device__ __align__(16) __nv_bfloat16 d_x16  [(size_t)2*SEG*HD];
__device__ __align__(16) __nv_bfloat16 d_hb16 [(size_t)2*SEG*HD4];
__device__ __align__(16) __nv_bfloat16 d_aow16[(size_t)6*HD*HD];
__device__ __align__(16) __nv_bfloat16 d_wvT16[(size_t)6*HD*HD];
__device__ __align__(16) __nv_bfloat16 d_Wc16 [(size_t)6*HD*HD];
__device__ __align__(16) __nv_bfloat16 d_ipw16[(size_t)2*HD*HD];
__device__ __align__(16) __nv_bfloat16 d_opw16[(size_t)2*HD*HD];
__device__ __align__(16) __nv_bfloat16 d_f1w16[(size_t)6*HD4*HD];
__device__ __align__(16) __nv_bfloat16 d_f2w16[(size_t)6*HD*HD4];

// ---------------- helpers ----------------
__device__ __forceinline__ float gelu_exact(float x){
    return 0.5f*x*(1.0f+erff(x*0.70710678118654752440f));
}
__device__ __forceinline__ unsigned int packbf(float a, float b){
    __nv_bfloat162 p; p.x = __float2bfloat16_rn(a); p.y = __float2bfloat16_rn(b);
    return *reinterpret_cast<unsigned int*>(&p);
}
__device__ __forceinline__ void cpasync16(unsigned int s, const void* g){
    asm volatile("cp.async.cg.shared.global [%0], [%1], 16;\n" :: "r"(s), "l"(g));
}
__device__ __forceinline__ void cpasync_commit(){
    asm volatile("cp.async.commit_group;\n");
}
__device__ __forceinline__ void cpasync_wait1(){
    asm volatile("cp.async.wait_group 1;\n" ::: "memory");
}
__device__ __forceinline__ void cpasync_wait0(){
    asm volatile("cp.async.wait_group 0;\n" ::: "memory");
}
__device__ __forceinline__ void ldsm_x4(unsigned int a, unsigned int &r0, unsigned int &r1,
                                        unsigned int &r2, unsigned int &r3){
    asm volatile("ldmatrix.sync.aligned.m8n8.x4.shared.b16 {%0,%1,%2,%3}, [%4];"
                 : "=r"(r0),"=r"(r1),"=r"(r2),"=r"(r3) : "r"(a));
}
__device__ __forceinline__ void mma_bf16(float* d, const unsigned int* a, const unsigned int* b){
    asm volatile(
        "mma.sync.aligned.m16n8k16.row.col.f32.bf16.bf16.f32 "
        "{%0,%1,%2,%3}, {%4,%5,%6,%7}, {%8,%9}, {%0,%1,%2,%3};"
        : "+f"(d[0]),"+f"(d[1]),"+f"(d[2]),"+f"(d[3])
        : "r"(a[0]),"r"(a[1]),"r"(a[2]),"r"(a[3]),"r"(b[0]),"r"(b[1]));
}

// ---------------- bf16 GEMM: C[z][M,N] = A[z]@W[z]^T + bias ----------------
// EPI: 0 none, 1 gelu.  OUTM: 0 fp32 only, 1 fp32+bf16 shadow, 2 bf16 only.
// 3-stage cp.async ring, one __syncthreads per K-iteration.
template<int EPI, int OUTM>
__global__ void __launch_bounds__(256, 2) mm16(
    const __nv_bfloat16* __restrict__ A, size_t As_,
    const __nv_bfloat16* __restrict__ W, size_t Ws_,
    const float* __restrict__ bias, size_t bs_,
    float* __restrict__ C, __nv_bfloat16* __restrict__ C16, size_t Cs_,
    int N, int K, int Mstatic, const int* __restrict__ cnt)
{
    const int z  = blockIdx.z;
    const int Mv = cnt ? cnt[z] : Mstatic;
    const int m0 = blockIdx.y * BM;
    if (m0 >= Mv) return;
    const int n0 = blockIdx.x * BN;
    A += (size_t)z * As_;
    W += (size_t)z * Ws_;
    if (OUTM != 2) C   += (size_t)z * Cs_;
    if (OUTM != 0) C16 += (size_t)z * Cs_;
    const float* bptr = bias ? (bias + (size_t)z * bs_) : nullptr;

    extern __shared__ __nv_bfloat16 smem16[];
    const unsigned int smem_u32 = (unsigned int)__cvta_generic_to_shared(smem16);

    const int tid  = threadIdx.x;
    const int wid  = tid >> 5;
    const int lane = tid & 31;
    const int wm   = wid & 1;
    const int wn   = wid >> 1;

    const int arow = (lane & 7) + ((lane >> 3) & 1) * 8;
    const int acol = ((lane >> 4) & 1) * 8;
    const int brow = (lane & 7) + ((lane >> 4) & 1) * 8;
    const int bcol = ((lane >> 3) & 1) * 8;

    unsigned int a_off[4], b_off[2];
    #pragma unroll
    for (int i=0;i<4;i++) a_off[i] = (unsigned int)(((wm*64 + i*16 + arow)*PADE + acol)*2);
    #pragma unroll
    for (int p=0;p<2;p++) b_off[p] = (unsigned int)((BM*PADE + (wn*32 + p*16 + brow)*PADE + bcol)*2);

    float acc[4][4][4];
    #pragma unroll
    for (int i=0;i<4;i++)
        #pragma unroll
        for (int j=0;j<4;j++)
            #pragma unroll
            for (int r=0;r<4;r++) acc[i][j][r]=0.f;

    auto load_stage = [&](int s, int k0){
        const unsigned int base = smem_u32 + (unsigned int)(s*STAGE_EL*2);
        #pragma unroll
        for (int it=0; it<4; it++){
            int c  = tid + it*256;          // 0..1023
            int r  = c >> 3;                // 0..127
            int kq = (c & 7) * 8;           // element offset
            unsigned int off = (unsigned int)((r*PADE + kq)*2);
            cpasync16(base + off,                                &A[(size_t)(m0+r)*K + k0 + kq]);
            cpasync16(base + (unsigned int)(BM*PADE*2) + off,    &W[(size_t)(n0+r)*K + k0 + kq]);
        }
        cpasync_commit();
    };

    const int NIT = K / BK;
    load_stage(0, 0);
    load_stage(1, BK);

    for (int i=0; i<NIT; i++){
        if (i < NIT-1) cpasync_wait1(); else cpasync_wait0();
        __syncthreads();
        if (i + 2 < NIT) load_stage((i+2)%3, (i+2)*BK);

        const unsigned int sb = smem_u32 + (unsigned int)((i%3)*STAGE_EL*2);
        #pragma unroll
        for (int kk=0; kk<BK; kk+=16){
            unsigned int a[4][4], b[4][2];
            #pragma unroll
            for (int ii=0;ii<4;ii++)
                ldsm_x4(sb + a_off[ii] + (unsigned int)(kk*2), a[ii][0],a[ii][1],a[ii][2],a[ii][3]);
            #pragma unroll
            for (int p=0;p<2;p++)
                ldsm_x4(sb + b_off[p] + (unsigned int)(kk*2),
                        b[2*p][0], b[2*p][1], b[2*p+1][0], b[2*p+1][1]);
            #pragma unroll
            for (int ii=0;ii<4;ii++)
                #pragma unroll
                for (int j=0;j<4;j++)
                    mma_bf16(acc[ii][j], a[ii], b[j]);
        }
    }

    const int g   = lane >> 2;
    const int tig = lane & 3;
    #pragma unroll
    for (int i=0;i<4;i++){
        int row0 = m0 + wm*64 + i*16 + g;
        int row1 = row0 + 8;
        #pragma unroll
        for (int j=0;j<4;j++){
            int col = n0 + wn*32 + j*8 + 2*tig;
            float b0 = bptr ? bptr[col]   : 0.f;
            float b1 = bptr ? bptr[col+1] : 0.f;
            float v0 = acc[i][j][0] + b0, v1 = acc[i][j][1] + b1;
            float v2 = acc[i][j][2] + b0, v3 = acc[i][j][3] + b1;
            if (EPI==1){ v0=gelu_exact(v0); v1=gelu_exact(v1); v2=gelu_exact(v2); v3=gelu_exact(v3); }
            if (row0 < Mv){
                if (OUTM != 2) *(float2*)&C[(size_t)row0*N + col] = make_float2(v0,v1);
                if (OUTM != 0) *(unsigned int*)&C16[(size_t)row0*N + col] = packbf(v0,v1);
            }
            if (row1 < Mv){
                if (OUTM != 2) *(float2*)&C[(size_t)row1*N + col] = make_float2(v2,v3);
                if (OUTM != 0) *(unsigned int*)&C16[(size_t)row1*N + col] = packbf(v2,v3);
            }
        }
    }
}

// ---------------- fused bf16 GEMM + residual + LayerNorm (N = 512) ----------------
// 2-stage ring, one __syncthreads per iteration.
__global__ void __launch_bounds__(256, 1) mm16_ln(
    const __nv_bfloat16* __restrict__ A, size_t As_,
    const __nv_bfloat16* __restrict__ W, size_t Ws_,
    const float* __restrict__ bias, size_t bs_,
    const float* __restrict__ Xres, size_t Xs_,
    const float* __restrict__ lng, const float* __restrict__ lnb, size_t lns_,
    float* __restrict__ Out, __nv_bfloat16* __restrict__ Out16, size_t Os_,
    int K, const int* __restrict__ cnt)
{
    const int z  = blockIdx.z;
    const int Mv = cnt[z];
    const int m0 = blockIdx.y * BMF;
    if (m0 >= Mv) return;
    A     += (size_t)z * As_;
    W     += (size_t)z * Ws_;
    Xres  += (size_t)z * Xs_;
    Out   += (size_t)z * Os_;
    Out16 += (size_t)z * Os_;
    const float* bptr = bias + (size_t)z * bs_;
    const float* gptr = lng  + (size_t)z * lns_;
    const float* hptr = lnb  + (size_t)z * lns_;

    extern __shared__ __nv_bfloat16 smem16[];
    const unsigned int smem_u32 = (unsigned int)__cvta_generic_to_shared(smem16);
    float* smf = reinterpret_cast<float*>(smem16);

    const int tid  = threadIdx.x;
    const int wid  = tid >> 5;
    const int lane = tid & 31;
    const int wm   = wid & 1;     // 2 m-halves of 32
    const int wn   = wid >> 1;    // 4 n-quarters of 128

    const int arow = (lane & 7) + ((lane >> 3) & 1) * 8;
    const int acol = ((lane >> 4) & 1) * 8;
    const int brow = (lane & 7) + ((lane >> 4) & 1) * 8;
    const int bcol = ((lane >> 3) & 1) * 8;

    unsigned int a_off[2], b_off[8];
    #pragma unroll
    for (int i=0;i<2;i++) a_off[i] = (unsigned int)(((wm*32 + i*16 + arow)*PADE + acol)*2);
    #pragma unroll
    for (int p=0;p<8;p++) b_off[p] = (unsigned int)((BMF*PADE + (wn*128 + p*16 + brow)*PADE + bcol)*2);

    float acc[2][16][4];
    #pragma unroll
    for (int i=0;i<2;i++)
        #pragma unroll
        for (int j=0;j<16;j++)
            #pragma unroll
            for (int r=0;r<4;r++) acc[i][j][r]=0.f;

    auto load_stage = [&](int s, int k0){
        const unsigned int base = smem_u32 + (unsigned int)(s*STF_EL*2);
        #pragma unroll
        for (int it=0; it<2; it++){
            int c  = tid + it*256;          // 0..511
            int r  = c >> 3;                // 0..63
            int kq = (c & 7) * 8;
            cpasync16(base + (unsigned int)((r*PADE + kq)*2), &A[(size_t)(m0+r)*K + k0 + kq]);
        }
        #pragma unroll
        for (int it=0; it<16; it++){
            int c  = tid + it*256;          // 0..4095
            int r  = c >> 3;                // 0..511
            int kq = (c & 7) * 8;
            cpasync16(base + (unsigned int)((BMF*PADE + r*PADE + kq)*2), &W[(size_t)r*K + k0 + kq]);
        }
        cpasync_commit();
    };

    const int NIT = K / BK;
    load_stage(0, 0);

    for (int i=0; i<NIT; i++){
        cpasync_wait0();
        __syncthreads();
        if (i + 1 < NIT) load_stage((i+1)&1, (i+1)*BK);

        const unsigned int sb = smem_u32 + (unsigned int)((i&1)*STF_EL*2);
        #pragma unroll
        for (int kk=0; kk<BK; kk+=16){
            unsigned int a[2][4], b[16][2];
            #pragma unroll
            for (int ii=0;ii<2;ii++)
                ldsm_x4(sb + a_off[ii] + (unsigned int)(kk*2), a[ii][0],a[ii][1],a[ii][2],a[ii][3]);
            #pragma unroll
            for (int p=0;p<8;p++)
                ldsm_x4(sb + b_off[p] + (unsigned int)(kk*2),
                        b[2*p][0], b[2*p][1], b[2*p+1][0], b[2*p+1][1]);
            #pragma unroll
            for (int ii=0;ii<2;ii++)
                #pragma unroll
                for (int j=0;j<16;j++)
                    mma_bf16(acc[ii][j], a[ii], b[j]);
        }
    }
    __syncthreads();   // protect smem reuse (LN reduction buffers) against lagging warps

    // ---- bias + residual into acc ----
    const int g   = lane >> 2;
    const int tig = lane & 3;
    #pragma unroll
    for (int i=0;i<2;i++){
        int row0 = m0 + wm*32 + i*16 + g;
        int row1 = row0 + 8;
        #pragma unroll
        for (int j=0;j<16;j++){
            int col = wn*128 + j*8 + 2*tig;
            float b0 = bptr[col], b1 = bptr[col+1];
            if (row0 < Mv){
                float2 x = *(const float2*)&Xres[(size_t)row0*HD + col];
                acc[i][j][0] += b0 + x.x;
                acc[i][j][1] += b1 + x.y;
            }
            if (row1 < Mv){
                float2 x = *(const float2*)&Xres[(size_t)row1*HD + col];
                acc[i][j][2] += b0 + x.x;
                acc[i][j][3] += b1 + x.y;
            }
        }
    }

    // ---- per-row stats ----
    float S[2][2], Q[2][2];
    #pragma unroll
    for (int i=0;i<2;i++)
        #pragma unroll
        for (int h=0;h<2;h++){
            float s=0.f, q=0.f;
            #pragma unroll
            for (int j=0;j<16;j++){
                float v0=acc[i][j][2*h], v1=acc[i][j][2*h+1];
                s += v0+v1; q += v0*v0+v1*v1;
            }
            s += __shfl_xor_sync(0xffffffffu, s, 1);
            s += __shfl_xor_sync(0xffffffffu, s, 2);
            q += __shfl_xor_sync(0xffffffffu, q, 1);
            q += __shfl_xor_sync(0xffffffffu, q, 2);
            S[i][h]=s; Q[i][h]=q;
        }
    float* redS = smf;          // [64][4]
    float* redQ = smf + 256;
    if (tig==0){
        #pragma unroll
        for (int i=0;i<2;i++)
            #pragma unroll
            for (int h=0;h<2;h++){
                int lr = wm*32 + i*16 + g + h*8;
                redS[lr*4+wn] = S[i][h];
                redQ[lr*4+wn] = Q[i][h];
            }
    }
    __syncthreads();

    // ---- normalize + dual store ----
    #pragma unroll
    for (int i=0;i<2;i++){
        #pragma unroll
        for (int h=0;h<2;h++){
            int lr  = wm*32 + i*16 + g + h*8;
            int row = m0 + lr;
            if (row >= Mv) continue;
            float s = redS[lr*4+0]+redS[lr*4+1]+redS[lr*4+2]+redS[lr*4+3];
            float q = redQ[lr*4+0]+redQ[lr*4+1]+redQ[lr*4+2]+redQ[lr*4+3];
            float mean = s*(1.f/512.f);
            float var  = q*(1.f/512.f) - mean*mean;
            float rs   = rsqrtf(var + 1e-5f);
            #pragma unroll
            for (int j=0;j<16;j++){
                int col = wn*128 + j*8 + 2*tig;
                float g0=gptr[col], g1=gptr[col+1], h0=hptr[col], h1=hptr[col+1];
                float v0=(acc[i][j][2*h  ]-mean)*rs*g0+h0;
                float v1=(acc[i][j][2*h+1]-mean)*rs*g1+h1;
                *(float2*)&Out[(size_t)row*HD + col] = make_float2(v0,v1);
                *(unsigned int*)&Out16[(size_t)row*HD + col] = packbf(v0,v1);
            }
        }
    }
}

// ---------------- helpers ----------------
__global__ void cvt_bf16_kernel(const float* __restrict__ src, __nv_bfloat16* __restrict__ dst, int n)
{
    int i = (blockIdx.x*blockDim.x + threadIdx.x)*4;
    if (i >= n) return;
    float4 v = *(const float4*)&src[i];
    *(uint2*)&dst[i] = make_uint2(packbf(v.x,v.y), packbf(v.z,v.w));
}

__global__ void build_index_kernel(const int* __restrict__ mt)
{
    if (threadIdx.x==0){ d_cnt[0]=0; d_cnt[1]=0; }
    __syncthreads();
    for (int b=threadIdx.x; b<BSZ; b+=blockDim.x){
        int m = mt[b];
        if (m==1){ int p=atomicAdd(&d_cnt[0],1); d_idx[0][p]=b; d_pos[0][b]=p; }
        else if (m==2){ int p=atomicAdd(&d_cnt[1],1); d_idx[1][p]=b; d_pos[1][b]=p; }
    }
}

__global__ void __launch_bounds__(128) gather_kernel(
    const float* __restrict__ img, const float* __restrict__ text)
{
    int gi = blockIdx.y;
    int c  = blockIdx.x;
    if (c >= d_cnt[gi]) return;
    int r = d_idx[gi][c];
    const float* src = gi ? text : img;
    const float* tgt = gi ? img  : text;
    int t = threadIdx.x;
    size_t drow = (size_t)gi*SEG + c;
    float4 sv = ((const float4*)src)[(size_t)r*128+t];
    float4 tv = ((const float4*)tgt)[(size_t)r*128+t];
    *(uint2*)&d_srcC16[drow*HD + t*4] = make_uint2(packbf(sv.x,sv.y), packbf(sv.z,sv.w));
    *(uint2*)&d_tgtC16[drow*HD + t*4] = make_uint2(packbf(tv.x,tv.y), packbf(tv.z,tv.w));
}

__global__ void transpose_wv_kernel(const float* __restrict__ qkv_w)
{
    __shared__ float tile[32][33];
    int bz = blockIdx.z;
    const float* src = qkv_w + (size_t)bz*3*HD*HD + (size_t)2*HD*HD;
    int j0 = blockIdx.y*32, k0 = blockIdx.x*32;
    int tx = threadIdx.x, ty = threadIdx.y;
    #pragma unroll
    for (int r=0;r<32;r+=8)
        tile[ty+r][tx] = src[(size_t)(j0+ty+r)*HD + k0+tx];
    __syncthreads();
    __nv_bfloat16* dst = d_wvT16 + (size_t)bz*HD*HD;
    #pragma unroll
    for (int r=0;r<32;r+=8)
        dst[(size_t)(k0+ty+r)*HD + j0+tx] = __float2bfloat16_rn(tile[tx][ty+r]);
}

__global__ void __launch_bounds__(256) bc_kernel(const float* __restrict__ ao_w,
                          const float* __restrict__ ao_b,
                          const float* __restrict__ qkv_b)
{
    int z = blockIdx.x;
    int n = blockIdx.y*8 + (threadIdx.x>>5);
    int lane = threadIdx.x&31;
    const float* ao = ao_w + (size_t)z*HD*HD + (size_t)n*HD;
    const float* bv = qkv_b + (size_t)z*3*HD + 2*HD;
    float s=0.f;
    #pragma unroll
    for (int j=lane*4;j<HD;j+=128){
        float4 a = *(const float4*)&ao[j];
        float4 b = *(const float4*)&bv[j];
        s += a.x*b.x + a.y*b.y + a.z*b.z + a.w*b.w;
    }
    #pragma unroll
    for (int off=16;off;off>>=1) s += __shfl_down_sync(0xffffffffu,s,off);
    if (lane==0) d_bc[(size_t)z*HD+n] = s + ao_b[(size_t)z*HD+n];
}

__global__ void prior_mm_kernel(const float* __restrict__ x, const float* __restrict__ W,
                                const float* __restrict__ b, float* __restrict__ out,
                                int K, int N, int dogelu)
{
    int gw = (blockIdx.x*blockDim.x + threadIdx.x)>>5;
    int lane = threadIdx.x & 31;
    if (gw >= N) return;
    float s=0.f;
    for (int k=lane;k<K;k+=32) s += x[k]*W[(size_t)gw*K+k];
    #pragma unroll
    for (int off=16;off;off>>=1) s += __shfl_down_sync(0xffffffffu,s,off);
    if (lane==0){ s += b[gw]; out[gw] = dogelu ? gelu_exact(s) : s; }
}

__global__ void __launch_bounds__(128) final_kernel(
    const float* __restrict__ img, const float* __restrict__ text,
    const int* __restrict__ mtA, const float* __restrict__ rw,
    float* __restrict__ out)
{
    int b = blockIdx.x, t = threadIdx.x;
    int mt = mtA[b];
    float4 iv = ((const float4*)img )[(size_t)b*128+t];
    float4 tv = ((const float4*)text)[(size_t)b*128+t];
    float4 oi = iv, ot = tv;
    if (mt==3){
        oi = ((const float4*)d_prior)[t];
        ot = ((const float4*)d_prior)[128+t];
    } else if (mt==2){
        float r = rw[1], q = 1.f - r;
        float4 gv = ((const float4*)d_genb)[((size_t)SEG + d_pos[1][b])*128+t];
        oi.x=r*iv.x+q*gv.x; oi.y=r*iv.y+q*gv.y; oi.z=r*iv.z+q*gv.z; oi.w=r*iv.w+q*gv.w;
    } else if (mt==1){
        float r = rw[0], q = 1.f - r;
        float4 gv = ((const float4*)d_genb)[(size_t)d_pos[0][b]*128+t];
        ot.x=r*tv.x+q*gv.x; ot.y=r*tv.y+q*gv.y; ot.z=r*tv.z+q*gv.z; ot.w=r*tv.w+q*gv.w;
    }
    ((float4*)out)[(size_t)b*128+t] = oi;
    ((float4*)out)[(size_t)BSZ*128 + (size_t)b*128+t] = ot;
}

// ---------------- host orchestration ----------------
extern "C" void kernel_launch(void* const* d_in, const int* in_sizes, int n_in,
                              void* d_out, int out_size)
{
    const float* img  = (const float*)d_in[0];
    const float* text = (const float*)d_in[1];
    const float* ipw  = (const float*)d_in[2];
    const float* ipb  = (const float*)d_in[3];
    const float* qkvw = (const float*)d_in[4];
    const float* qkvb = (const float*)d_in[5];
    const float* aow  = (const float*)d_in[6];
    const float* aob  = (const float*)d_in[7];
    const float* ln1g = (const float*)d_in[8];
    const float* ln1b = (const float*)d_in[9];
    const float* ln2g = (const float*)d_in[10];
    const float* ln2b = (const float*)d_in[11];
    const float* f1w  = (const float*)d_in[12];
    const float* f1b  = (const float*)d_in[13];
    const float* f2w  = (const float*)d_in[14];
    const float* f2b  = (const float*)d_in[15];
    const float* opw  = (const float*)d_in[16];
    const float* opb  = (const float*)d_in[17];
    const float* rw   = (const float*)d_in[18];
    const float* pw1  = (const float*)d_in[19];
    const float* pb1  = (const float*)d_in[20];
    const float* pw2  = (const float*)d_in[21];
    const float* pb2  = (const float*)d_in[22];
    const float* pemb = (const float*)d_in[23];
    const int*   mt   = (const int*)d_in[24];
    float* out = (float*)d_out;

    static int smem_set = 0;
    if (!smem_set){
        cudaFuncSetAttribute(mm16<0,0>, cudaFuncAttributeMaxDynamicSharedMemorySize, SMEM16_BYTES);
        cudaFuncSetAttribute(mm16<0,1>, cudaFuncAttributeMaxDynamicSharedMemorySize, SMEM16_BYTES);
        cudaFuncSetAttribute(mm16<0,2>, cudaFuncAttributeMaxDynamicSharedMemorySize, SMEM16_BYTES);
        cudaFuncSetAttribute(mm16<1,2>, cudaFuncAttributeMaxDynamicSharedMemorySize, SMEM16_BYTES);
        cudaFuncSetAttribute(mm16_ln,   cudaFuncAttributeMaxDynamicSharedMemorySize, SMEM_LN_BYTES);
        smem_set = 1;
    }

    void* p;
    cudaGetSymbolAddress(&p, d_bc);     float* bc   = (float*)p;
    cudaGetSymbolAddress(&p, d_cnt);    int*   cnt  = (int*)p;
    cudaGetSymbolAddress(&p, d_xbuf);   float* xb   = (float*)p;
    cudaGetSymbolAddress(&p, d_genb);   float* genb = (float*)p;
    cudaGetSymbolAddress(&p, d_prior_h);float* ph   = (float*)p;
    cudaGetSymbolAddress(&p, d_prior);  float* pr   = (float*)p;
    cudaGetSymbolAddress(&p, d_srcC16); __nv_bfloat16* srcC16 = (__nv_bfloat16*)p;
    cudaGetSymbolAddress(&p, d_tgtC16); __nv_bfloat16* tgtC16 = (__nv_bfloat16*)p;
    cudaGetSymbolAddress(&p, d_x16);    __nv_bfloat16* x16    = (__nv_bfloat16*)p;
    cudaGetSymbolAddress(&p, d_hb16);   __nv_bfloat16* hb16   = (__nv_bfloat16*)p;
    cudaGetSymbolAddress(&p, d_aow16);  __nv_bfloat16* aow16  = (__nv_bfloat16*)p;
    cudaGetSymbolAddress(&p, d_wvT16);  __nv_bfloat16* wvT16  = (__nv_bfloat16*)p;
    cudaGetSymbolAddress(&p, d_Wc16);   __nv_bfloat16* Wc16   = (__nv_bfloat16*)p;
    cudaGetSymbolAddress(&p, d_ipw16);  __nv_bfloat16* ipw16  = (__nv_bfloat16*)p;
    cudaGetSymbolAddress(&p, d_opw16);  __nv_bfloat16* opw16  = (__nv_bfloat16*)p;
    cudaGetSymbolAddress(&p, d_f1w16);  __nv_bfloat16* f1w16  = (__nv_bfloat16*)p;
    cudaGetSymbolAddress(&p, d_f2w16);  __nv_bfloat16* f2w16  = (__nv_bfloat16*)p;

    const size_t HH  = (size_t)HD*HD;
    const size_t SH  = (size_t)SEG*HD;
    const size_t SH4 = (size_t)SEG*HD4;

    auto cvt = [&](const float* s, __nv_bfloat16* d, size_t n){
        cvt_bf16_kernel<<<(unsigned)((n/4 + 255)/256), 256>>>(s, d, (int)n);
    };

    // 1) compaction + weight conversion + prep + prior
    build_index_kernel<<<1,256>>>(mt);
    cvt(aow, aow16, 6*HH);
    cvt(ipw, ipw16, 2*HH);
    cvt(opw, opw16, 2*HH);
    cvt(f1w, f1w16, (size_t)6*HD4*HD);
    cvt(f2w, f2w16, (size_t)6*HD*HD4);
    transpose_wv_kernel<<<dim3(16,16,6), dim3(32,8)>>>(qkvw);
    // Wc16[z] = aow16[z] @ wvT16[z]^T
    mm16<0,2><<<dim3(HD/BN, HD/BM, 6), 256, SMEM16_BYTES>>>(
        aow16, HH, wvT16, HH, nullptr, 0, nullptr, Wc16, HH, HD, HD, HD, nullptr);
    bc_kernel<<<dim3(6,64),256>>>(aow, aob, qkvb);
    prior_mm_kernel<<<128,256>>>(pemb, pw1, pb1, ph, HD,   2*HD, 1);
    prior_mm_kernel<<<128,256>>>(ph,   pw2, pb2, pr, 2*HD, 2*HD, 0);

    // 2) both generators batched over z=2 on compacted rows
    gather_kernel<<<dim3(BSZ,2),128>>>(img, text);

    const dim3 gN512 (HD /BN, BSZ/BM, 2);
    const dim3 gN2048(HD4/BN, BSZ/BM, 2);
    const dim3 gLN   (1, BSZ/BMF, 2);

    // x = srcC @ ipw^T + ipb   (fp32 + bf16 shadow)
    mm16<0,1><<<gN512,256,SMEM16_BYTES>>>(srcC16, SH, ipw16, HH, ipb, HD,
                                          xb, x16, SH, HD, HD, 0, cnt);
    for (int l=0;l<NL;l++){
        // x = LN1( x + tgtC @ Wc[l]^T + bc[l] )
        mm16_ln<<<gLN,256,SMEM_LN_BYTES>>>(tgtC16, SH, Wc16 + (size_t)l*HH, (size_t)NL*HH,
                                  bc + (size_t)l*HD, (size_t)NL*HD,
                                  xb, SH,
                                  ln1g + (size_t)l*HD, ln1b + (size_t)l*HD, (size_t)NL*HD,
                                  xb, x16, SH, HD, cnt);
        // h = gelu(x @ f1w^T + f1b)   (bf16 only)
        mm16<1,2><<<gN2048,256,SMEM16_BYTES>>>(x16, SH, f1w16 + (size_t)l*HD4*HD, (size_t)NL*HD4*HD,
                                   f1b + (size_t)l*HD4, (size_t)NL*HD4,
                                   nullptr, hb16, SH4, HD4, HD, 0, cnt);
        // x = LN2( x + h @ f2w^T + f2b )
        mm16_ln<<<gLN,256,SMEM_LN_BYTES>>>(hb16, SH4, f2w16 + (size_t)l*HD*HD4, (size_t)NL*HD*HD4,
                                  f2b + (size_t)l*HD, (size_t)NL*HD,
                                  xb, SH,
                                  ln2g + (size_t)l*HD, ln2b + (size_t)l*HD, (size_t)NL*HD,
                                  xb, x16, SH, HD4, cnt);
    }
    // gen core = x @ opw^T + opb   (fp32 only)
    mm16<0,0><<<gN512,256,SMEM16_BYTES>>>(x16, SH, opw16, HH, opb, HD,
                                          genb, nullptr, SH, HD, HD, 0, cnt);

    // 3) final selection/blend
    final_kernel<<<BSZ,128>>>(img, text, mt, rw, out);
}